// round 5
// baseline (speedup 1.0000x reference)
#include <cuda_runtime.h>
#include <math.h>

// ---------------------------------------------------------------------------
// Shapes (fixed): x: [8,3,128,128]; encoder spatial 64x64. BH = 8*64 = 512.
// ---------------------------------------------------------------------------

#define BH 512

// ------------------------------- scratch -----------------------------------
__device__ float g_bufA[16777216];   // [8,512,64,64]
__device__ float g_bufB[16777216];   // [8,512,64,64]
__device__ float g_bufT[4194304];    // [8,128,64,64]
__device__ float g_bufZ[8388608];    // [8,256,64,64]

__device__ float g_pw1 [1179648];    // conv1  packed [9][256][512]
__device__ float g_pw2 [2359296];    // conv2  packed [9][512][512]
__device__ float g_pwE1[9437184];    // enc res w1 packed [16][9][512][128]
__device__ float g_pwE2[1048576];    // enc res w2 packed [16][128][512]
__device__ float g_pw3 [1179648];    // conv3  packed [9][512][256]
__device__ float g_pwD0[1179648];    // dec conv0 packed [9][256][512]
__device__ float g_pwDr1[9437184];   // dec res w1 packed
__device__ float g_pwDr2[1048576];   // dec res w2 packed
__device__ float g_pwD1[1179648];    // dec conv1 packed [9][512][256]
__device__ float g_cbT [262144];     // codebook^T [256][1024]
__device__ float g_cnorm[1024];
__device__ float g_znorm[32768];
__device__ unsigned long long g_bestkey[32768];
__device__ float g_bnscale[512];
__device__ float g_bnshift[512];
__device__ float g_vqsum;
__device__ float g_reconsum;

// ---------------------------- small helpers --------------------------------
__device__ __forceinline__ float warpReduceSum(float v) {
#pragma unroll
    for (int s = 16; s > 0; s >>= 1) v += __shfl_down_sync(0xffffffffu, v, s);
    return v;
}

union F4U2 { float4 f; unsigned long long u[2]; };
union U2F2 { unsigned long long u; float2 f; };

__device__ __forceinline__ void fma2(unsigned long long& d,
                                     unsigned long long a, unsigned long long b) {
    asm("fma.rn.f32x2 %0, %1, %2, %0;" : "+l"(d) : "l"(a), "l"(b));
}

// ------------------------------ pack kernels -------------------------------
// src: [blk][Cout][Cin][3][3]  ->  dst: [blk][9][Cin][Cout]
__global__ void pack3x3_k(const float* __restrict__ src, float* __restrict__ dst,
                          int nblk, int Cin, int Cout) {
    long long total = (long long)nblk * Cout * Cin * 9;
    for (long long i = (long long)blockIdx.x * blockDim.x + threadIdx.x; i < total;
         i += (long long)gridDim.x * blockDim.x) {
        int r = (int)(i % 9);
        long long t = i / 9;
        int ci = (int)(t % Cin); t /= Cin;
        int co = (int)(t % Cout);
        int blk = (int)(t / Cout);
        dst[(((long long)blk * 9 + r) * Cin + ci) * Cout + co] = src[i];
    }
}

// src: [blk][Cout][Cin]  ->  dst: [blk][Cin][Cout]
__global__ void pack1x1_k(const float* __restrict__ src, float* __restrict__ dst,
                          int nblk, int Cin, int Cout) {
    long long total = (long long)nblk * Cout * Cin;
    for (long long i = (long long)blockIdx.x * blockDim.x + threadIdx.x; i < total;
         i += (long long)gridDim.x * blockDim.x) {
        int ci = (int)(i % Cin);
        long long t = i / Cin;
        int co = (int)(t % Cout);
        int blk = (int)(t / Cout);
        dst[((long long)blk * Cin + ci) * Cout + co] = src[i];
    }
}

// codebook [1024][256] -> cbT [256][1024]
__global__ void packT_k(const float* __restrict__ src, float* __restrict__ dst) {
    int i = blockIdx.x * blockDim.x + threadIdx.x;   // 262144 total
    if (i < 262144) {
        int d = i & 255, k = i >> 8;
        dst[d * 1024 + k] = src[i];
    }
}

__global__ void init_k(unsigned long long* bestkey, float* vqsum, float* reconsum) {
    int i = blockIdx.x * blockDim.x + threadIdx.x;
    if (i < 32768) bestkey[i] = 0xFFFFFFFFFFFFFFFFull;
    if (i == 0) { *vqsum = 0.f; *reconsum = 0.f; }
}

__global__ void cnorm_k(const float* __restrict__ cb, float* __restrict__ cn) {
    int k = blockIdx.x;          // 1024 blocks, 256 threads
    float v = cb[k * 256 + threadIdx.x];
    float p = warpReduceSum(v * v);
    __shared__ float sh[8];
    if ((threadIdx.x & 31) == 0) sh[threadIdx.x >> 5] = p;
    __syncthreads();
    if (threadIdx.x == 0) {
        float t = 0.f;
#pragma unroll
        for (int i = 0; i < 8; i++) t += sh[i];
        cn[k] = t;
    }
}

// per-pixel ||z||^2 over D=256 (z layout [B][256][64][64])
__global__ void znorm_k(const float* __restrict__ z, float* __restrict__ zn) {
    int n = blockIdx.x * blockDim.x + threadIdx.x;   // 32768
    if (n >= 32768) return;
    int b = n >> 12, rem = n & 4095;
    const float* zp = z + (((size_t)b * 256) << 12) + rem;
    float s = 0.f;
#pragma unroll 8
    for (int d = 0; d < 256; d++) {
        float v = zp[(size_t)d << 12];
        s = fmaf(v, v, s);
    }
    zn[n] = s;
}

// ------------------------------ conv0 (4x4 s2) ------------------------------
__global__ void conv0_k(const float* __restrict__ x, const float* __restrict__ w,
                        const float* __restrict__ bias, float* __restrict__ out) {
    int idx = blockIdx.x * blockDim.x + threadIdx.x;     // 8*256*64*64
    if (idx >= 8388608) return;
    int ox = idx & 63, oy = (idx >> 6) & 63, co = (idx >> 12) & 255, b = idx >> 20;
    float acc = bias[co];
    const float* wc = w + co * 48;
#pragma unroll
    for (int c = 0; c < 3; c++) {
        const float* xp = x + (size_t)(b * 3 + c) * 16384;
#pragma unroll
        for (int ky = 0; ky < 4; ky++) {
            int iy = oy * 2 - 1 + ky;
            if (iy < 0 || iy >= 128) continue;
#pragma unroll
            for (int kx = 0; kx < 4; kx++) {
                int ix = ox * 2 - 1 + kx;
                if (ix < 0 || ix >= 128) continue;
                acc = fmaf(xp[iy * 128 + ix], wc[c * 16 + ky * 4 + kx], acc);
            }
        }
    }
    out[idx] = acc;
}

// ------------------------------- batchnorm ----------------------------------
__global__ void bn_stats_k(const float* __restrict__ buf, const float* __restrict__ g,
                           const float* __restrict__ bb, int C,
                           float* __restrict__ scale, float* __restrict__ shift) {
    int c = blockIdx.x;
    int tid = threadIdx.x;
    double s = 0.0, s2 = 0.0;
    for (int t = tid; t < 8 * 4096; t += 256) {
        int b = t >> 12, off = t & 4095;
        float v = buf[(((size_t)b * C + c) << 12) + off];
        s += (double)v; s2 += (double)v * v;
    }
    __shared__ double sh[256], sh2[256];
    sh[tid] = s; sh2[tid] = s2;
    __syncthreads();
    for (int st = 128; st; st >>= 1) {
        if (tid < st) { sh[tid] += sh[tid + st]; sh2[tid] += sh2[tid + st]; }
        __syncthreads();
    }
    if (tid == 0) {
        double m = sh[0] / 32768.0;
        double v = sh2[0] / 32768.0 - m * m;
        double sc = (double)g[c] / sqrt(v + 1e-5);
        scale[c] = (float)sc;
        shift[c] = (float)((double)bb[c] - m * sc);
    }
}

__global__ void bn_apply_k(float* __restrict__ buf, const float* __restrict__ scale,
                           const float* __restrict__ shift, int C, int total) {
    int i = blockIdx.x * blockDim.x + threadIdx.x;
    if (i >= total) return;
    int c = (i >> 12) % C;
    buf[i] = fmaxf(fmaf(buf[i], scale[c], shift[c]), 0.f);
}

__global__ void relu_ip_k(float* __restrict__ buf, int total) {
    int i = blockIdx.x * blockDim.x + threadIdx.x;
    if (i < total) buf[i] = fmaxf(buf[i], 0.f);
}

// --------------------------- 3x3 conv (implicit GEMM, f32x2) ----------------
// Tile: 128 Cout x 64 pixels (one image row). 256 threads.
// Per thread: 8 Cout x 4 px accumulators held as 4x4 packed f32x2 (pair = Cout).
// X tile stored DUPLICATED in smem so (b,b) broadcast pairs load directly.
// wp layout: [9][Cin][Cout]; in/out: [B][C][64][64].
template <bool RELU_IN, bool RELU_OUT>
__global__ void __launch_bounds__(256)
conv3x3_k(const float* __restrict__ in, const float* __restrict__ wp,
          const float* __restrict__ bias, float* __restrict__ out,
          int Cin, int Cout) {
    const int cout0 = blockIdx.x * 128;
    const int by = blockIdx.y;
    const int b = by >> 6, y = by & 63;
    const int tid = threadIdx.x;
    const int tx = tid & 15, ty = tid >> 4;

    __shared__ __align__(16) float Ws[16][128];
    __shared__ __align__(16) float Xd[16][128];   // duplicated: [k][2p]=[k][2p+1]=x_p

    unsigned long long acc2[4][4];
#pragma unroll
    for (int i = 0; i < 4; i++)
#pragma unroll
        for (int j = 0; j < 4; j++) acc2[i][j] = 0ull;

    const int l = tid * 4;
    const int kW = l >> 7, coW = l & 127;        // W fill (2 slabs)
    const int kXf = tid >> 4;                    // X fill row 0..15
    const int colX = (tid * 8) & 127;            // duplicated column base
    const int p0 = colX >> 1;                    // source pixel base

    for (int r = 0; r < 9; ++r) {
        const int dy = r / 3 - 1, dx = r % 3 - 1;
        const int iy = y + dy;
        if (iy < 0 || iy >= 64) continue;        // uniform per block
        const float* wtap = wp + (size_t)r * Cin * Cout;
        const float* inrow = in + (size_t)b * Cin * 4096 + (size_t)iy * 64;
        for (int c0 = 0; c0 < Cin; c0 += 16) {
            __syncthreads();
            *(float4*)&Ws[kW][coW] =
                *(const float4*)(wtap + (size_t)(c0 + kW) * Cout + cout0 + coW);
            *(float4*)&Ws[kW + 8][coW] =
                *(const float4*)(wtap + (size_t)(c0 + kW + 8) * Cout + cout0 + coW);
            {
                const float* src = inrow + (size_t)(c0 + kXf) * 4096;
                float v[4];
#pragma unroll
                for (int j = 0; j < 4; j++) {
                    int xx = p0 + j + dx;
                    float vv = (xx >= 0 && xx < 64) ? src[xx] : 0.f;
                    if (RELU_IN) vv = fmaxf(vv, 0.f);
                    v[j] = vv;
                }
                *(float4*)&Xd[kXf][colX]     = make_float4(v[0], v[0], v[1], v[1]);
                *(float4*)&Xd[kXf][colX + 4] = make_float4(v[2], v[2], v[3], v[3]);
            }
            __syncthreads();
#pragma unroll
            for (int k = 0; k < 16; k++) {
                F4U2 A0, A1, B0, B1;
                A0.f = *(const float4*)&Ws[k][ty * 8];
                A1.f = *(const float4*)&Ws[k][ty * 8 + 4];
                B0.f = *(const float4*)&Xd[k][tx * 8];
                B1.f = *(const float4*)&Xd[k][tx * 8 + 4];
                const unsigned long long pa[4] = {A0.u[0], A0.u[1], A1.u[0], A1.u[1]};
                const unsigned long long pb[4] = {B0.u[0], B0.u[1], B1.u[0], B1.u[1]};
#pragma unroll
                for (int i = 0; i < 4; i++)
#pragma unroll
                    for (int j = 0; j < 4; j++)
                        fma2(acc2[i][j], pa[i], pb[j]);
            }
        }
    }

#pragma unroll
    for (int i2 = 0; i2 < 4; i2++) {
        U2F2 t0, t1, t2, t3;
        t0.u = acc2[i2][0]; t1.u = acc2[i2][1];
        t2.u = acc2[i2][2]; t3.u = acc2[i2][3];
#pragma unroll
        for (int half = 0; half < 2; half++) {
            const int co = cout0 + ty * 8 + i2 * 2 + half;
            const float bs = bias[co];
            float* orow = out + (((size_t)b * Cout + co) * 64 + y) * 64;
            float4 o4;
            o4.x = (half ? t0.f.y : t0.f.x) + bs;
            o4.y = (half ? t1.f.y : t1.f.x) + bs;
            o4.z = (half ? t2.f.y : t2.f.x) + bs;
            o4.w = (half ? t3.f.y : t3.f.x) + bs;
            if (RELU_OUT) {
                o4.x = fmaxf(o4.x, 0.f); o4.y = fmaxf(o4.y, 0.f);
                o4.z = fmaxf(o4.z, 0.f); o4.w = fmaxf(o4.w, 0.f);
            }
            *(float4*)(orow + tx * 4) = o4;
        }
    }
}

// --------------------- 1x1 conv + residual add (f32x2) -----------------------
__global__ void __launch_bounds__(256)
conv1x1_acc_k(const float* __restrict__ in, const float* __restrict__ wp,
              const float* __restrict__ bias, float* __restrict__ out,
              int Cin, int Cout) {
    const int cout0 = blockIdx.x * 128;
    const int by = blockIdx.y;
    const int b = by >> 6, y = by & 63;
    const int tid = threadIdx.x;
    const int tx = tid & 15, ty = tid >> 4;

    __shared__ __align__(16) float Ws[16][128];
    __shared__ __align__(16) float Xd[16][128];

    unsigned long long acc2[4][4];
#pragma unroll
    for (int i = 0; i < 4; i++)
#pragma unroll
        for (int j = 0; j < 4; j++) acc2[i][j] = 0ull;

    const int l = tid * 4;
    const int kW = l >> 7, coW = l & 127;
    const int kXf = tid >> 4;
    const int colX = (tid * 8) & 127;
    const int p0 = colX >> 1;
    const float* inrow = in + (size_t)b * Cin * 4096 + (size_t)y * 64;

    for (int c0 = 0; c0 < Cin; c0 += 16) {
        __syncthreads();
        *(float4*)&Ws[kW][coW] =
            *(const float4*)(wp + (size_t)(c0 + kW) * Cout + cout0 + coW);
        *(float4*)&Ws[kW + 8][coW] =
            *(const float4*)(wp + (size_t)(c0 + kW + 8) * Cout + cout0 + coW);
        {
            const float4 s = *(const float4*)(inrow + (size_t)(c0 + kXf) * 4096 + p0);
            *(float4*)&Xd[kXf][colX]     = make_float4(s.x, s.x, s.y, s.y);
            *(float4*)&Xd[kXf][colX + 4] = make_float4(s.z, s.z, s.w, s.w);
        }
        __syncthreads();
#pragma unroll
        for (int k = 0; k < 16; k++) {
            F4U2 A0, A1, B0, B1;
            A0.f = *(const float4*)&Ws[k][ty * 8];
            A1.f = *(const float4*)&Ws[k][ty * 8 + 4];
            B0.f = *(const float4*)&Xd[k][tx * 8];
            B1.f = *(const float4*)&Xd[k][tx * 8 + 4];
            const unsigned long long pa[4] = {A0.u[0], A0.u[1], A1.u[0], A1.u[1]};
            const unsigned long long pb[4] = {B0.u[0], B0.u[1], B1.u[0], B1.u[1]};
#pragma unroll
            for (int i = 0; i < 4; i++)
#pragma unroll
                for (int j = 0; j < 4; j++)
                    fma2(acc2[i][j], pa[i], pb[j]);
        }
    }

#pragma unroll
    for (int i2 = 0; i2 < 4; i2++) {
        U2F2 t0, t1, t2, t3;
        t0.u = acc2[i2][0]; t1.u = acc2[i2][1];
        t2.u = acc2[i2][2]; t3.u = acc2[i2][3];
#pragma unroll
        for (int half = 0; half < 2; half++) {
            const int co = cout0 + ty * 8 + i2 * 2 + half;
            const float bs = bias[co];
            float* orow = out + (((size_t)b * Cout + co) * 64 + y) * 64;
            float4 cur = *(float4*)(orow + tx * 4);
            cur.x += (half ? t0.f.y : t0.f.x) + bs;
            cur.y += (half ? t1.f.y : t1.f.x) + bs;
            cur.z += (half ? t2.f.y : t2.f.x) + bs;
            cur.w += (half ? t3.f.y : t3.f.x) + bs;
            *(float4*)(orow + tx * 4) = cur;
        }
    }
}

// ------------------------------- VQ argmin -----------------------------------
// Tile: 64 vectors (one row) x 64 codes; D=256 in chunks of 16.
// Score replicates the reference's fp32 rounding: (||z||^2 - 2*dot) + ||c||^2.
__global__ void __launch_bounds__(256)
vq_argmin_k(const float* __restrict__ z, const float* __restrict__ cbT,
            const float* __restrict__ cn, const float* __restrict__ zn,
            unsigned long long* __restrict__ bestkey) {
    const int code0 = blockIdx.x * 64;
    const int by = blockIdx.y;
    const int b = by >> 6, y = by & 63;
    const int tid = threadIdx.x;
    const int tx = tid & 15, ty = tid >> 4;

    __shared__ __align__(16) float Cs[16][64];
    __shared__ __align__(16) float Zs[16][64];
    __shared__ unsigned long long red[16][64];

    float acc[4][4];
#pragma unroll
    for (int i = 0; i < 4; i++)
#pragma unroll
        for (int j = 0; j < 4; j++) acc[i][j] = 0.f;

    const int l = tid * 4;
    const int k = l >> 6, c = l & 63;

    for (int d0 = 0; d0 < 256; d0 += 16) {
        __syncthreads();
        *(float4*)&Cs[k][c] = *(const float4*)&cbT[(size_t)(d0 + k) * 1024 + code0 + c];
        *(float4*)&Zs[k][c] =
            *(const float4*)&z[(((size_t)b * 256 + d0 + k) * 64 + y) * 64 + c];
        __syncthreads();
#pragma unroll
        for (int kk = 0; kk < 16; kk++) {
            const float4 av = *(const float4*)&Cs[kk][ty * 4];
            const float4 bv = *(const float4*)&Zs[kk][tx * 4];
            const float ai[4] = {av.x, av.y, av.z, av.w};
            const float bj[4] = {bv.x, bv.y, bv.z, bv.w};
#pragma unroll
            for (int i = 0; i < 4; i++)
#pragma unroll
                for (int j = 0; j < 4; j++)
                    acc[i][j] = fmaf(ai[i], bj[j], acc[i][j]);
        }
    }

#pragma unroll
    for (int j = 0; j < 4; j++) {
        const float znv = zn[by * 64 + tx * 4 + j];
        unsigned long long best = 0xFFFFFFFFFFFFFFFFull;
#pragma unroll
        for (int i = 0; i < 4; i++) {
            const int code = code0 + ty * 4 + i;
            const float s = (znv - 2.f * acc[i][j]) + cn[code];
            unsigned int u = __float_as_uint(s);
            unsigned int k32 = (u >> 31) ? ~u : (u | 0x80000000u);
            unsigned long long key = ((unsigned long long)k32 << 32) | (unsigned int)code;
            best = (key < best) ? key : best;
        }
        red[ty][tx * 4 + j] = best;
    }
    __syncthreads();
    for (int st = 8; st; st >>= 1) {
        if (ty < st) {
#pragma unroll
            for (int j = 0; j < 4; j++) {
                unsigned long long a = red[ty][tx * 4 + j];
                unsigned long long b2 = red[ty + st][tx * 4 + j];
                red[ty][tx * 4 + j] = (b2 < a) ? b2 : a;
            }
        }
        __syncthreads();
    }
    if (ty == 0) {
#pragma unroll
        for (int j = 0; j < 4; j++)
            atomicMin(&bestkey[by * 64 + tx * 4 + j], red[0][tx * 4 + j]);
    }
}

// q gather + straight-through output + vq loss accumulation.
__global__ void vq_gather_k(const float* __restrict__ z, const float* __restrict__ cb,
                            const unsigned long long* __restrict__ bestkey,
                            float* __restrict__ zq, float* __restrict__ vqsum) {
    const int n = blockIdx.x;                 // 32768
    const int d = threadIdx.x;                // 256
    const int idx = (int)(bestkey[n] & 0xFFFFFFFFull);
    const int b = n >> 12, rem = n & 4095;
    const float q = cb[idx * 256 + d];
    const size_t zoff = (((size_t)b * 256 + d) << 12) + rem;
    const float zv = z[zoff];
    const float diff = q - zv;
    zq[zoff] = zv + diff;   // straight-through: zf + (q - zf), reference rounding
    float p = warpReduceSum(diff * diff);
    __shared__ float sh[8];
    if ((threadIdx.x & 31) == 0) sh[threadIdx.x >> 5] = p;
    __syncthreads();
    if (threadIdx.x == 0) {
        float t = 0.f;
#pragma unroll
        for (int i = 0; i < 8; i++) t += sh[i];
        atomicAdd(vqsum, t);
    }
}

// -------------------------------- deconv -------------------------------------
__global__ void deconv_k(const float* __restrict__ in, const float* __restrict__ w,
                         const float* __restrict__ bias, const float* __restrict__ x,
                         float* __restrict__ out, float* __restrict__ reconsum) {
    const int idx = blockIdx.x * blockDim.x + threadIdx.x;   // 8*3*128*128
    if (idx >= 393216) return;
    const int ox = idx & 127, oy = (idx >> 7) & 127;
    const int bo = idx >> 14;
    const int o = bo % 3, b = bo / 3;
    float acc = bias[o];
    const int kyp = (oy + 1) & 1, kxp = (ox + 1) & 1;
#pragma unroll
    for (int t = 0; t < 4; t++) {
        const int ky = kyp + 2 * (t >> 1);
        const int kx = kxp + 2 * (t & 1);
        const int ny = oy + 1 - ky, nx = ox + 1 - kx;
        if (ny < 0 || nx < 0) continue;
        const int iy = ny >> 1, ix = nx >> 1;
        if (iy >= 64 || ix >= 64) continue;
        const float* ip = in + (size_t)b * 256 * 4096 + iy * 64 + ix;
        const float* wpp = w + o * 16 + ky * 4 + kx;
        float a = 0.f;
        for (int c2 = 0; c2 < 256; c2++)
            a = fmaf(ip[(size_t)c2 * 4096], wpp[c2 * 48], a);
        acc += a;
    }
    out[idx] = acc;
    const float d = acc - x[idx];
    float p = warpReduceSum(d * d);
    if ((threadIdx.x & 31) == 0) atomicAdd(reconsum, p);
}

__global__ void finalize_k(float* __restrict__ out, const float* __restrict__ vqsum,
                           const float* __restrict__ reconsum) {
    const float recon = *reconsum * (1.f / 393216.f);
    const float vq = 1.25f * (*vqsum) * (1.f / 8388608.f);
    out[393216] = recon + vq;
    out[393217] = recon;
}

// --------------------------------- launch ------------------------------------
extern "C" void kernel_launch(void* const* d_in, const int* in_sizes, int n_in,
                              void* d_out, int out_size) {
    const float* x          = (const float*)d_in[0];
    const float* ec0_w      = (const float*)d_in[1];
    const float* ec0_b      = (const float*)d_in[2];
    const float* ebn0_g     = (const float*)d_in[3];
    const float* ebn0_b     = (const float*)d_in[4];
    const float* ec1_w      = (const float*)d_in[5];
    const float* ec1_b      = (const float*)d_in[6];
    const float* ebn1_g     = (const float*)d_in[7];
    const float* ebn1_b     = (const float*)d_in[8];
    const float* ec2_w      = (const float*)d_in[9];
    const float* ec2_b      = (const float*)d_in[10];
    const float* er_w1      = (const float*)d_in[11];
    const float* er_b1      = (const float*)d_in[12];
    const float* er_w2      = (const float*)d_in[13];
    const float* er_b2      = (const float*)d_in[14];
    const float* ec3_w      = (const float*)d_in[15];
    const float* ec3_b      = (const float*)d_in[16];
    const float* codebook   = (const float*)d_in[17];
    const float* dc0_w      = (const float*)d_in[18];
    const float* dc0_b      = (const float*)d_in[19];
    const float* dr_w1      = (const float*)d_in[20];
    const float* dr_b1      = (const float*)d_in[21];
    const float* dr_w2      = (const float*)d_in[22];
    const float* dr_b2      = (const float*)d_in[23];
    const float* dc1_w      = (const float*)d_in[24];
    const float* dc1_b      = (const float*)d_in[25];
    const float* dd_w       = (const float*)d_in[26];
    const float* dd_b       = (const float*)d_in[27];
    float* out = (float*)d_out;

    float *bufA, *bufB, *bufT, *bufZ;
    float *pw1, *pw2, *pwE1, *pwE2, *pw3, *pwD0, *pwDr1, *pwDr2, *pwD1;
    float *cbT, *cn, *zn, *bnsc, *bnsh, *vqsum, *reconsum;
    unsigned long long* bestkey;
    cudaGetSymbolAddress((void**)&bufA, g_bufA);
    cudaGetSymbolAddress((void**)&bufB, g_bufB);
    cudaGetSymbolAddress((void**)&bufT, g_bufT);
    cudaGetSymbolAddress((void**)&bufZ, g_bufZ);
    cudaGetSymbolAddress((void**)&pw1,  g_pw1);
    cudaGetSymbolAddress((void**)&pw2,  g_pw2);
    cudaGetSymbolAddress((void**)&pwE1, g_pwE1);
    cudaGetSymbolAddress((void**)&pwE2, g_pwE2);
    cudaGetSymbolAddress((void**)&pw3,  g_pw3);
    cudaGetSymbolAddress((void**)&pwD0, g_pwD0);
    cudaGetSymbolAddress((void**)&pwDr1, g_pwDr1);
    cudaGetSymbolAddress((void**)&pwDr2, g_pwDr2);
    cudaGetSymbolAddress((void**)&pwD1, g_pwD1);
    cudaGetSymbolAddress((void**)&cbT,  g_cbT);
    cudaGetSymbolAddress((void**)&cn,   g_cnorm);
    cudaGetSymbolAddress((void**)&zn,   g_znorm);
    cudaGetSymbolAddress((void**)&bnsc, g_bnscale);
    cudaGetSymbolAddress((void**)&bnsh, g_bnshift);
    cudaGetSymbolAddress((void**)&vqsum, g_vqsum);
    cudaGetSymbolAddress((void**)&reconsum, g_reconsum);
    cudaGetSymbolAddress((void**)&bestkey, g_bestkey);

    // ---- weight repack + init ----
    pack3x3_k<<<4096, 256>>>(ec1_w, pw1, 1, 256, 512);
    pack3x3_k<<<4096, 256>>>(ec2_w, pw2, 1, 512, 512);
    pack3x3_k<<<8192, 256>>>(er_w1, pwE1, 16, 512, 128);
    pack1x1_k<<<2048, 256>>>(er_w2, pwE2, 16, 128, 512);
    pack3x3_k<<<4096, 256>>>(ec3_w, pw3, 1, 512, 256);
    pack3x3_k<<<4096, 256>>>(dc0_w, pwD0, 1, 256, 512);
    pack3x3_k<<<8192, 256>>>(dr_w1, pwDr1, 16, 512, 128);
    pack1x1_k<<<2048, 256>>>(dr_w2, pwDr2, 16, 128, 512);
    pack3x3_k<<<4096, 256>>>(dc1_w, pwD1, 1, 512, 256);
    packT_k<<<1024, 256>>>(codebook, cbT);
    init_k<<<128, 256>>>(bestkey, vqsum, reconsum);
    cnorm_k<<<1024, 256>>>(codebook, cn);

    // ---- encoder ----
    conv0_k<<<32768, 256>>>(x, ec0_w, ec0_b, bufZ);
    bn_stats_k<<<256, 256>>>(bufZ, ebn0_g, ebn0_b, 256, bnsc, bnsh);
    bn_apply_k<<<32768, 256>>>(bufZ, bnsc, bnsh, 256, 8 * 256 * 4096);

    conv3x3_k<false, false><<<dim3(4, BH), 256>>>(bufZ, pw1, ec1_b, bufA, 256, 512);
    bn_stats_k<<<512, 256>>>(bufA, ebn1_g, ebn1_b, 512, bnsc, bnsh);
    bn_apply_k<<<65536, 256>>>(bufA, bnsc, bnsh, 512, 8 * 512 * 4096);

    conv3x3_k<false, false><<<dim3(4, BH), 256>>>(bufA, pw2, ec2_b, bufB, 512, 512);

    for (int blk = 0; blk < 16; blk++) {
        conv3x3_k<true, true><<<dim3(1, BH), 256>>>(
            bufB, pwE1 + (size_t)blk * 9 * 512 * 128, er_b1 + blk * 128, bufT, 512, 128);
        conv1x1_acc_k<<<dim3(4, BH), 256>>>(
            bufT, pwE2 + (size_t)blk * 128 * 512, er_b2 + blk * 512, bufB, 128, 512);
        if ((blk & 3) == 3)
            relu_ip_k<<<65536, 256>>>(bufB, 8 * 512 * 4096);
    }

    conv3x3_k<false, false><<<dim3(2, BH), 256>>>(bufB, pw3, ec3_b, bufZ, 512, 256);

    // ---- vector quantizer ----
    znorm_k<<<128, 256>>>(bufZ, zn);
    vq_argmin_k<<<dim3(16, BH), 256>>>(bufZ, cbT, cn, zn, bestkey);
    vq_gather_k<<<32768, 256>>>(bufZ, codebook, bestkey, bufA, vqsum);

    // ---- decoder ----
    conv3x3_k<false, false><<<dim3(4, BH), 256>>>(bufA, pwD0, dc0_b, bufB, 256, 512);

    for (int blk = 0; blk < 16; blk++) {
        conv3x3_k<true, true><<<dim3(1, BH), 256>>>(
            bufB, pwDr1 + (size_t)blk * 9 * 512 * 128, dr_b1 + blk * 128, bufT, 512, 128);
        conv1x1_acc_k<<<dim3(4, BH), 256>>>(
            bufT, pwDr2 + (size_t)blk * 128 * 512, dr_b2 + blk * 512, bufB, 128, 512);
        if ((blk & 3) == 3)
            relu_ip_k<<<65536, 256>>>(bufB, 8 * 512 * 4096);
    }

    conv3x3_k<false, true><<<dim3(2, BH), 256>>>(bufB, pwD1, dc1_b, bufZ, 512, 256);

    deconv_k<<<1536, 256>>>(bufZ, dd_w, dd_b, x, out, reconsum);
    finalize_k<<<1, 1>>>(out, vqsum, reconsum);
}

// round 6
// speedup vs baseline: 4.0315x; 4.0315x over previous
#include <cuda_runtime.h>
#include <math.h>

// ---------------------------------------------------------------------------
// VQ-VAE forward. x: [8,3,128,128]; encoder spatial 64x64. BH = 8*64 = 512.
// All 3x3 convs run as Winograd F(2x2,3x3): 32x32=1024 tiles/image, 8192 total.
// ---------------------------------------------------------------------------

#define BH 512
#define NTILES 8192   // 8 images * 32*32 tiles

// ------------------------------- scratch -----------------------------------
__device__ float g_bufA[16777216];   // [8,512,64,64]
__device__ float g_bufB[16777216];   // [8,512,64,64]
__device__ float g_bufT[4194304];    // [8,128,64,64]
__device__ float g_bufZ[8388608];    // [8,256,64,64]

__device__ float g_V[67108864];      // winograd input  [16][512][8192]
__device__ float g_M[67108864];      // winograd output [16][Cout][8192]

__device__ float g_u1 [2097152];     // conv1  U [16][256][512]
__device__ float g_u2 [4194304];     // conv2  U [16][512][512]
__device__ float g_u3 [2097152];     // conv3  U [16][512][256]
__device__ float g_uD0[2097152];     // dec c0 U [16][256][512]
__device__ float g_uD1[2097152];     // dec c1 U [16][512][256]
__device__ float g_uE1[16777216];    // enc res U [16 lay][16][512][128]
__device__ float g_uDr1[16777216];   // dec res U [16 lay][16][512][128]

__device__ float g_pwE2[1048576];    // enc res w2 packed [16][128][512]
__device__ float g_pwDr2[1048576];   // dec res w2 packed

__device__ float g_cbT [262144];     // codebook^T [256][1024]
__device__ float g_cnorm[1024];
__device__ float g_znorm[32768];
__device__ unsigned long long g_bestkey[32768];
__device__ float g_bnscale[512];
__device__ float g_bnshift[512];
__device__ float g_vqsum;
__device__ float g_reconsum;

// ---------------------------- small helpers --------------------------------
__device__ __forceinline__ float warpReduceSum(float v) {
#pragma unroll
    for (int s = 16; s > 0; s >>= 1) v += __shfl_down_sync(0xffffffffu, v, s);
    return v;
}

// ------------------------------ pack kernels -------------------------------
// src: [blk][Cout][Cin]  ->  dst: [blk][Cin][Cout]
__global__ void pack1x1_k(const float* __restrict__ src, float* __restrict__ dst,
                          int nblk, int Cin, int Cout) {
    long long total = (long long)nblk * Cout * Cin;
    for (long long i = (long long)blockIdx.x * blockDim.x + threadIdx.x; i < total;
         i += (long long)gridDim.x * blockDim.x) {
        int ci = (int)(i % Cin);
        long long t = i / Cin;
        int co = (int)(t % Cout);
        int blk = (int)(t / Cout);
        dst[((long long)blk * Cin + ci) * Cout + co] = src[i];
    }
}

// Winograd weight transform: w [nblk][Cout][Cin][3][3] -> U [nblk][16][Cin][Cout]
__global__ void wtrans_k(const float* __restrict__ w, float* __restrict__ U,
                         int nblk, int Cin, int Cout) {
    long long total = (long long)nblk * Cout * Cin;
    long long idx = (long long)blockIdx.x * blockDim.x + threadIdx.x;
    if (idx >= total) return;
    int ci = (int)(idx % Cin);
    long long rest = idx / Cin;
    int co = (int)(rest % Cout);
    int blk = (int)(rest / Cout);
    const float* g = w + idx * 9;
    float gg[3][3];
#pragma unroll
    for (int i = 0; i < 3; i++)
#pragma unroll
        for (int j = 0; j < 3; j++) gg[i][j] = g[i * 3 + j];
    float tu[4][3];
#pragma unroll
    for (int j = 0; j < 3; j++) {
        tu[0][j] = gg[0][j];
        tu[1][j] = 0.5f * (gg[0][j] + gg[1][j] + gg[2][j]);
        tu[2][j] = 0.5f * (gg[0][j] - gg[1][j] + gg[2][j]);
        tu[3][j] = gg[2][j];
    }
#pragma unroll
    for (int i = 0; i < 4; i++) {
        float u0 = tu[i][0];
        float u1 = 0.5f * (tu[i][0] + tu[i][1] + tu[i][2]);
        float u2 = 0.5f * (tu[i][0] - tu[i][1] + tu[i][2]);
        float u3 = tu[i][2];
        size_t base = (((size_t)blk * 16 + i * 4) * Cin + ci) * Cout + co;
        size_t pl = (size_t)Cin * Cout;
        U[base]          = u0;
        U[base + pl]     = u1;
        U[base + 2 * pl] = u2;
        U[base + 3 * pl] = u3;
    }
}

// codebook [1024][256] -> cbT [256][1024]
__global__ void packT_k(const float* __restrict__ src, float* __restrict__ dst) {
    int i = blockIdx.x * blockDim.x + threadIdx.x;
    if (i < 262144) {
        int d = i & 255, k = i >> 8;
        dst[d * 1024 + k] = src[i];
    }
}

__global__ void init_k(unsigned long long* bestkey, float* vqsum, float* reconsum) {
    int i = blockIdx.x * blockDim.x + threadIdx.x;
    if (i < 32768) bestkey[i] = 0xFFFFFFFFFFFFFFFFull;
    if (i == 0) { *vqsum = 0.f; *reconsum = 0.f; }
}

__global__ void cnorm_k(const float* __restrict__ cb, float* __restrict__ cn) {
    int k = blockIdx.x;
    float v = cb[k * 256 + threadIdx.x];
    float p = warpReduceSum(v * v);
    __shared__ float sh[8];
    if ((threadIdx.x & 31) == 0) sh[threadIdx.x >> 5] = p;
    __syncthreads();
    if (threadIdx.x == 0) {
        float t = 0.f;
#pragma unroll
        for (int i = 0; i < 8; i++) t += sh[i];
        cn[k] = t;
    }
}

// per-pixel ||z||^2 over D=256
__global__ void znorm_k(const float* __restrict__ z, float* __restrict__ zn) {
    int n = blockIdx.x * blockDim.x + threadIdx.x;
    if (n >= 32768) return;
    int b = n >> 12, rem = n & 4095;
    const float* zp = z + (((size_t)b * 256) << 12) + rem;
    float s = 0.f;
#pragma unroll 8
    for (int d = 0; d < 256; d++) {
        float v = zp[(size_t)d << 12];
        s = fmaf(v, v, s);
    }
    zn[n] = s;
}

// ------------------------------ conv0 (4x4 s2) ------------------------------
__global__ void conv0_k(const float* __restrict__ x, const float* __restrict__ w,
                        const float* __restrict__ bias, float* __restrict__ out) {
    int idx = blockIdx.x * blockDim.x + threadIdx.x;
    if (idx >= 8388608) return;
    int ox = idx & 63, oy = (idx >> 6) & 63, co = (idx >> 12) & 255, b = idx >> 20;
    float acc = bias[co];
    const float* wc = w + co * 48;
#pragma unroll
    for (int c = 0; c < 3; c++) {
        const float* xp = x + (size_t)(b * 3 + c) * 16384;
#pragma unroll
        for (int ky = 0; ky < 4; ky++) {
            int iy = oy * 2 - 1 + ky;
            if (iy < 0 || iy >= 128) continue;
#pragma unroll
            for (int kx = 0; kx < 4; kx++) {
                int ix = ox * 2 - 1 + kx;
                if (ix < 0 || ix >= 128) continue;
                acc = fmaf(xp[iy * 128 + ix], wc[c * 16 + ky * 4 + kx], acc);
            }
        }
    }
    out[idx] = acc;
}

// ------------------------------- batchnorm ----------------------------------
__global__ void bn_stats_k(const float* __restrict__ buf, const float* __restrict__ g,
                           const float* __restrict__ bb, int C,
                           float* __restrict__ scale, float* __restrict__ shift) {
    int c = blockIdx.x;
    int tid = threadIdx.x;
    double s = 0.0, s2 = 0.0;
    for (int t = tid; t < 8 * 4096; t += 256) {
        int b = t >> 12, off = t & 4095;
        float v = buf[(((size_t)b * C + c) << 12) + off];
        s += (double)v; s2 += (double)v * v;
    }
    __shared__ double sh[256], sh2[256];
    sh[tid] = s; sh2[tid] = s2;
    __syncthreads();
    for (int st = 128; st; st >>= 1) {
        if (tid < st) { sh[tid] += sh[tid + st]; sh2[tid] += sh2[tid + st]; }
        __syncthreads();
    }
    if (tid == 0) {
        double m = sh[0] / 32768.0;
        double v = sh2[0] / 32768.0 - m * m;
        double sc = (double)g[c] / sqrt(v + 1e-5);
        scale[c] = (float)sc;
        shift[c] = (float)((double)bb[c] - m * sc);
    }
}

__global__ void bn_apply_k(float* __restrict__ buf, const float* __restrict__ scale,
                           const float* __restrict__ shift, int C, int total) {
    int i = blockIdx.x * blockDim.x + threadIdx.x;
    if (i >= total) return;
    int c = (i >> 12) % C;
    buf[i] = fmaxf(fmaf(buf[i], scale[c], shift[c]), 0.f);
}

__global__ void relu_ip_k(float* __restrict__ buf, int total) {
    int i = blockIdx.x * blockDim.x + threadIdx.x;
    if (i < total) buf[i] = fmaxf(buf[i], 0.f);
}

// ---------------------- Winograd F(2x2,3x3): input transform ----------------
// in: [8][Cin][64][64] -> V[r=16][512 fixed stride][8192 tiles]
template <bool RELU>
__global__ void win_in_k(const float* __restrict__ in, float* __restrict__ V, int Cin) {
    int idx = blockIdx.x * 256 + threadIdx.x;      // Cin * 8192
    if (idx >= (Cin << 13)) return;
    int tile = idx & 8191, ci = idx >> 13;
    int b = tile >> 10, t = tile & 1023, ty = t >> 5, tx = t & 31;
    const float* src = in + (((size_t)b * Cin + ci) << 12);
    const int iy0 = 2 * ty - 1, ix0 = 2 * tx - 1;
    float d[4][4];
#pragma unroll
    for (int i = 0; i < 4; i++) {
        int iy = iy0 + i;
        bool yok = (iy >= 0 && iy < 64);
#pragma unroll
        for (int j = 0; j < 4; j++) {
            int ix = ix0 + j;
            float v = (yok && ix >= 0 && ix < 64) ? src[iy * 64 + ix] : 0.f;
            if (RELU) v = fmaxf(v, 0.f);
            d[i][j] = v;
        }
    }
    float tr[4][4];
#pragma unroll
    for (int j = 0; j < 4; j++) {
        tr[0][j] = d[0][j] - d[2][j];
        tr[1][j] = d[1][j] + d[2][j];
        tr[2][j] = d[2][j] - d[1][j];
        tr[3][j] = d[1][j] - d[3][j];
    }
#pragma unroll
    for (int i = 0; i < 4; i++) {
        float v0 = tr[i][0] - tr[i][2];
        float v1 = tr[i][1] + tr[i][2];
        float v2 = tr[i][2] - tr[i][1];
        float v3 = tr[i][1] - tr[i][3];
        size_t base = (((size_t)(i * 4) * 512 + ci) << 13) + tile;
        V[base]               = v0;
        V[base + (512u << 13)]     = v1;
        V[base + (size_t)2 * (512u << 13)] = v2;
        V[base + (size_t)3 * (512u << 13)] = v3;
    }
}

// ---------------------- Winograd batched GEMM (scalar FFMA core) ------------
// M[r][co][tile] = sum_ci U[r][ci][co] * V[r][ci][tile]
__global__ void __launch_bounds__(256)
win_gemm_k(const float* __restrict__ U, const float* __restrict__ V,
           float* __restrict__ M, int Cin, int Cout) {
    const int coutTiles = Cout >> 7;
    const int r = blockIdx.x / coutTiles;
    const int co0 = (blockIdx.x % coutTiles) * 128;
    const int tile0 = blockIdx.y * 64;
    const int tid = threadIdx.x;
    const int tx = tid & 15, ty = tid >> 4;

    __shared__ __align__(16) float Ws[16][128];
    __shared__ __align__(16) float Xs[16][64];

    float acc[8][4];
#pragma unroll
    for (int i = 0; i < 8; i++)
#pragma unroll
        for (int j = 0; j < 4; j++) acc[i][j] = 0.f;

    const int l = tid * 4;
    const int kW = l >> 7, coW = l & 127;
    const int kX = l >> 6, pxX = l & 63;

    const float* Ur = U + (size_t)r * Cin * Cout;
    const float* Vr = V + ((size_t)r * 512 << 13);

    for (int c0 = 0; c0 < Cin; c0 += 16) {
        __syncthreads();
        *(float4*)&Ws[kW][coW] =
            *(const float4*)(Ur + (size_t)(c0 + kW) * Cout + co0 + coW);
        *(float4*)&Ws[kW + 8][coW] =
            *(const float4*)(Ur + (size_t)(c0 + kW + 8) * Cout + co0 + coW);
        *(float4*)&Xs[kX][pxX] =
            *(const float4*)(Vr + ((size_t)(c0 + kX) << 13) + tile0 + pxX);
        __syncthreads();
#pragma unroll
        for (int k = 0; k < 16; k++) {
            const float4 bv = *(const float4*)&Xs[k][tx * 4];
            const float4 a0 = *(const float4*)&Ws[k][ty * 8];
            const float4 a1 = *(const float4*)&Ws[k][ty * 8 + 4];
            const float bj[4] = {bv.x, bv.y, bv.z, bv.w};
            const float ai[8] = {a0.x, a0.y, a0.z, a0.w, a1.x, a1.y, a1.z, a1.w};
#pragma unroll
            for (int i = 0; i < 8; i++)
#pragma unroll
                for (int j = 0; j < 4; j++)
                    acc[i][j] = fmaf(ai[i], bj[j], acc[i][j]);
        }
    }

#pragma unroll
    for (int i = 0; i < 8; i++) {
        const int co = co0 + ty * 8 + i;
        float* orow = M + (((size_t)r * Cout + co) << 13) + tile0;
        *(float4*)(orow + tx * 4) = make_float4(acc[i][0], acc[i][1], acc[i][2], acc[i][3]);
    }
}

// ---------------------- Winograd inverse transform + bias (+relu) -----------
template <bool RELU>
__global__ void win_out_k(const float* __restrict__ M, const float* __restrict__ bias,
                          float* __restrict__ out, int Cout) {
    int idx = blockIdx.x * 256 + threadIdx.x;      // Cout * 8192
    if (idx >= (Cout << 13)) return;
    int tile = idx & 8191, co = idx >> 13;
    float m[4][4];
#pragma unroll
    for (int i = 0; i < 4; i++)
#pragma unroll
        for (int j = 0; j < 4; j++)
            m[i][j] = M[(((size_t)(i * 4 + j) * Cout + co) << 13) + tile];
    float t0[4], t1[4];
#pragma unroll
    for (int j = 0; j < 4; j++) {
        t0[j] = m[0][j] + m[1][j] + m[2][j];
        t1[j] = m[1][j] - m[2][j] - m[3][j];
    }
    const float bs = bias[co];
    float o00 = t0[0] + t0[1] + t0[2] + bs;
    float o01 = t0[1] - t0[2] - t0[3] + bs;
    float o10 = t1[0] + t1[1] + t1[2] + bs;
    float o11 = t1[1] - t1[2] - t1[3] + bs;
    if (RELU) {
        o00 = fmaxf(o00, 0.f); o01 = fmaxf(o01, 0.f);
        o10 = fmaxf(o10, 0.f); o11 = fmaxf(o11, 0.f);
    }
    int b = tile >> 10, t = tile & 1023, ty = t >> 5, tx = t & 31;
    float* dst = out + (((size_t)b * Cout + co) << 12) + (2 * ty) * 64 + 2 * tx;
    dst[0] = o00; dst[1] = o01;
    dst[64] = o10; dst[65] = o11;
}

// --------------------- 1x1 conv + residual add (scalar) ----------------------
__global__ void __launch_bounds__(256)
conv1x1_acc_k(const float* __restrict__ in, const float* __restrict__ wp,
              const float* __restrict__ bias, float* __restrict__ out,
              int Cin, int Cout) {
    const int cout0 = blockIdx.x * 128;
    const int by = blockIdx.y;
    const int b = by >> 6, y = by & 63;
    const int tid = threadIdx.x;
    const int tx = tid & 15, ty = tid >> 4;

    __shared__ __align__(16) float Ws[16][128];
    __shared__ __align__(16) float Xs[16][64];

    float acc[8][4];
#pragma unroll
    for (int i = 0; i < 8; i++)
#pragma unroll
        for (int j = 0; j < 4; j++) acc[i][j] = 0.f;

    const int l = tid * 4;
    const int kW = l >> 7, coW = l & 127;
    const int kX = l >> 6, pxX = l & 63;
    const float* inrow = in + (size_t)b * Cin * 4096 + (size_t)y * 64;

    for (int c0 = 0; c0 < Cin; c0 += 16) {
        __syncthreads();
        *(float4*)&Ws[kW][coW] =
            *(const float4*)(wp + (size_t)(c0 + kW) * Cout + cout0 + coW);
        *(float4*)&Ws[kW + 8][coW] =
            *(const float4*)(wp + (size_t)(c0 + kW + 8) * Cout + cout0 + coW);
        *(float4*)&Xs[kX][pxX] =
            *(const float4*)(inrow + (size_t)(c0 + kX) * 4096 + pxX);
        __syncthreads();
#pragma unroll
        for (int k = 0; k < 16; k++) {
            const float4 bv = *(const float4*)&Xs[k][tx * 4];
            const float4 a0 = *(const float4*)&Ws[k][ty * 8];
            const float4 a1 = *(const float4*)&Ws[k][ty * 8 + 4];
            const float bj[4] = {bv.x, bv.y, bv.z, bv.w};
            const float ai[8] = {a0.x, a0.y, a0.z, a0.w, a1.x, a1.y, a1.z, a1.w};
#pragma unroll
            for (int i = 0; i < 8; i++)
#pragma unroll
                for (int j = 0; j < 4; j++)
                    acc[i][j] = fmaf(ai[i], bj[j], acc[i][j]);
        }
    }

#pragma unroll
    for (int i = 0; i < 8; i++) {
        const int co = cout0 + ty * 8 + i;
        const float bs = bias[co];
        float* orow = out + (((size_t)b * Cout + co) * 64 + y) * 64;
        float4 cur = *(float4*)(orow + tx * 4);
        cur.x += acc[i][0] + bs; cur.y += acc[i][1] + bs;
        cur.z += acc[i][2] + bs; cur.w += acc[i][3] + bs;
        *(float4*)(orow + tx * 4) = cur;
    }
}

// ------------------------------- VQ argmin -----------------------------------
__global__ void __launch_bounds__(256)
vq_argmin_k(const float* __restrict__ z, const float* __restrict__ cbT,
            const float* __restrict__ cn, const float* __restrict__ zn,
            unsigned long long* __restrict__ bestkey) {
    const int code0 = blockIdx.x * 64;
    const int by = blockIdx.y;
    const int b = by >> 6, y = by & 63;
    const int tid = threadIdx.x;
    const int tx = tid & 15, ty = tid >> 4;

    __shared__ __align__(16) float Cs[16][64];
    __shared__ __align__(16) float Zs[16][64];
    __shared__ unsigned long long red[16][64];

    float acc[4][4];
#pragma unroll
    for (int i = 0; i < 4; i++)
#pragma unroll
        for (int j = 0; j < 4; j++) acc[i][j] = 0.f;

    const int l = tid * 4;
    const int k = l >> 6, c = l & 63;

    for (int d0 = 0; d0 < 256; d0 += 16) {
        __syncthreads();
        *(float4*)&Cs[k][c] = *(const float4*)&cbT[(size_t)(d0 + k) * 1024 + code0 + c];
        *(float4*)&Zs[k][c] =
            *(const float4*)&z[(((size_t)b * 256 + d0 + k) * 64 + y) * 64 + c];
        __syncthreads();
#pragma unroll
        for (int kk = 0; kk < 16; kk++) {
            const float4 av = *(const float4*)&Cs[kk][ty * 4];
            const float4 bv = *(const float4*)&Zs[kk][tx * 4];
            const float ai[4] = {av.x, av.y, av.z, av.w};
            const float bj[4] = {bv.x, bv.y, bv.z, bv.w};
#pragma unroll
            for (int i = 0; i < 4; i++)
#pragma unroll
                for (int j = 0; j < 4; j++)
                    acc[i][j] = fmaf(ai[i], bj[j], acc[i][j]);
        }
    }

#pragma unroll
    for (int j = 0; j < 4; j++) {
        const float znv = zn[by * 64 + tx * 4 + j];
        unsigned long long best = 0xFFFFFFFFFFFFFFFFull;
#pragma unroll
        for (int i = 0; i < 4; i++) {
            const int code = code0 + ty * 4 + i;
            const float s = (znv - 2.f * acc[i][j]) + cn[code];
            unsigned int u = __float_as_uint(s);
            unsigned int k32 = (u >> 31) ? ~u : (u | 0x80000000u);
            unsigned long long key = ((unsigned long long)k32 << 32) | (unsigned int)code;
            best = (key < best) ? key : best;
        }
        red[ty][tx * 4 + j] = best;
    }
    __syncthreads();
    for (int st = 8; st; st >>= 1) {
        if (ty < st) {
#pragma unroll
            for (int j = 0; j < 4; j++) {
                unsigned long long a = red[ty][tx * 4 + j];
                unsigned long long b2 = red[ty + st][tx * 4 + j];
                red[ty][tx * 4 + j] = (b2 < a) ? b2 : a;
            }
        }
        __syncthreads();
    }
    if (ty == 0) {
#pragma unroll
        for (int j = 0; j < 4; j++)
            atomicMin(&bestkey[by * 64 + tx * 4 + j], red[0][tx * 4 + j]);
    }
}

__global__ void vq_gather_k(const float* __restrict__ z, const float* __restrict__ cb,
                            const unsigned long long* __restrict__ bestkey,
                            float* __restrict__ zq, float* __restrict__ vqsum) {
    const int n = blockIdx.x;
    const int d = threadIdx.x;
    const int idx = (int)(bestkey[n] & 0xFFFFFFFFull);
    const int b = n >> 12, rem = n & 4095;
    const float q = cb[idx * 256 + d];
    const size_t zoff = (((size_t)b * 256 + d) << 12) + rem;
    const float zv = z[zoff];
    const float diff = q - zv;
    zq[zoff] = zv + diff;
    float p = warpReduceSum(diff * diff);
    __shared__ float sh[8];
    if ((threadIdx.x & 31) == 0) sh[threadIdx.x >> 5] = p;
    __syncthreads();
    if (threadIdx.x == 0) {
        float t = 0.f;
#pragma unroll
        for (int i = 0; i < 8; i++) t += sh[i];
        atomicAdd(vqsum, t);
    }
}

// -------------------------------- deconv -------------------------------------
__global__ void deconv_k(const float* __restrict__ in, const float* __restrict__ w,
                         const float* __restrict__ bias, const float* __restrict__ x,
                         float* __restrict__ out, float* __restrict__ reconsum) {
    const int idx = blockIdx.x * blockDim.x + threadIdx.x;
    if (idx >= 393216) return;
    const int ox = idx & 127, oy = (idx >> 7) & 127;
    const int bo = idx >> 14;
    const int o = bo % 3, b = bo / 3;
    float acc = bias[o];
    const int kyp = (oy + 1) & 1, kxp = (ox + 1) & 1;
#pragma unroll
    for (int t = 0; t < 4; t++) {
        const int ky = kyp + 2 * (t >> 1);
        const int kx = kxp + 2 * (t & 1);
        const int ny = oy + 1 - ky, nx = ox + 1 - kx;
        if (ny < 0 || nx < 0) continue;
        const int iy = ny >> 1, ix = nx >> 1;
        if (iy >= 64 || ix >= 64) continue;
        const float* ip = in + (size_t)b * 256 * 4096 + iy * 64 + ix;
        const float* wpp = w + o * 16 + ky * 4 + kx;
        float a = 0.f;
        for (int c2 = 0; c2 < 256; c2++)
            a = fmaf(ip[(size_t)c2 * 4096], wpp[c2 * 48], a);
        acc += a;
    }
    out[idx] = acc;
    const float d = acc - x[idx];
    float p = warpReduceSum(d * d);
    if ((threadIdx.x & 31) == 0) atomicAdd(reconsum, p);
}

__global__ void finalize_k(float* __restrict__ out, const float* __restrict__ vqsum,
                           const float* __restrict__ reconsum) {
    const float recon = *reconsum * (1.f / 393216.f);
    const float vq = 1.25f * (*vqsum) * (1.f / 8388608.f);
    out[393216] = recon + vq;
    out[393217] = recon;
}

// --------------------------------- launch ------------------------------------
extern "C" void kernel_launch(void* const* d_in, const int* in_sizes, int n_in,
                              void* d_out, int out_size) {
    const float* x          = (const float*)d_in[0];
    const float* ec0_w      = (const float*)d_in[1];
    const float* ec0_b      = (const float*)d_in[2];
    const float* ebn0_g     = (const float*)d_in[3];
    const float* ebn0_b     = (const float*)d_in[4];
    const float* ec1_w      = (const float*)d_in[5];
    const float* ec1_b      = (const float*)d_in[6];
    const float* ebn1_g     = (const float*)d_in[7];
    const float* ebn1_b     = (const float*)d_in[8];
    const float* ec2_w      = (const float*)d_in[9];
    const float* ec2_b      = (const float*)d_in[10];
    const float* er_w1      = (const float*)d_in[11];
    const float* er_b1      = (const float*)d_in[12];
    const float* er_w2      = (const float*)d_in[13];
    const float* er_b2      = (const float*)d_in[14];
    const float* ec3_w      = (const float*)d_in[15];
    const float* ec3_b      = (const float*)d_in[16];
    const float* codebook   = (const float*)d_in[17];
    const float* dc0_w      = (const float*)d_in[18];
    const float* dc0_b      = (const float*)d_in[19];
    const float* dr_w1      = (const float*)d_in[20];
    const float* dr_b1      = (const float*)d_in[21];
    const float* dr_w2      = (const float*)d_in[22];
    const float* dr_b2      = (const float*)d_in[23];
    const float* dc1_w      = (const float*)d_in[24];
    const float* dc1_b      = (const float*)d_in[25];
    const float* dd_w       = (const float*)d_in[26];
    const float* dd_b       = (const float*)d_in[27];
    float* out = (float*)d_out;

    float *bufA, *bufB, *bufT, *bufZ, *V, *M;
    float *u1, *u2, *u3, *uD0, *uD1, *uE1, *uDr1, *pwE2, *pwDr2;
    float *cbT, *cn, *zn, *bnsc, *bnsh, *vqsum, *reconsum;
    unsigned long long* bestkey;
    cudaGetSymbolAddress((void**)&bufA, g_bufA);
    cudaGetSymbolAddress((void**)&bufB, g_bufB);
    cudaGetSymbolAddress((void**)&bufT, g_bufT);
    cudaGetSymbolAddress((void**)&bufZ, g_bufZ);
    cudaGetSymbolAddress((void**)&V,    g_V);
    cudaGetSymbolAddress((void**)&M,    g_M);
    cudaGetSymbolAddress((void**)&u1,   g_u1);
    cudaGetSymbolAddress((void**)&u2,   g_u2);
    cudaGetSymbolAddress((void**)&u3,   g_u3);
    cudaGetSymbolAddress((void**)&uD0,  g_uD0);
    cudaGetSymbolAddress((void**)&uD1,  g_uD1);
    cudaGetSymbolAddress((void**)&uE1,  g_uE1);
    cudaGetSymbolAddress((void**)&uDr1, g_uDr1);
    cudaGetSymbolAddress((void**)&pwE2, g_pwE2);
    cudaGetSymbolAddress((void**)&pwDr2, g_pwDr2);
    cudaGetSymbolAddress((void**)&cbT,  g_cbT);
    cudaGetSymbolAddress((void**)&cn,   g_cnorm);
    cudaGetSymbolAddress((void**)&zn,   g_znorm);
    cudaGetSymbolAddress((void**)&bnsc, g_bnscale);
    cudaGetSymbolAddress((void**)&bnsh, g_bnshift);
    cudaGetSymbolAddress((void**)&vqsum, g_vqsum);
    cudaGetSymbolAddress((void**)&reconsum, g_reconsum);
    cudaGetSymbolAddress((void**)&bestkey, g_bestkey);

    const size_t resU = (size_t)16 * 512 * 128;   // per res layer U size

    // ---- weight transforms + packs + init ----
    wtrans_k<<<512, 256>>>(ec1_w, u1, 1, 256, 512);
    wtrans_k<<<1024, 256>>>(ec2_w, u2, 1, 512, 512);
    wtrans_k<<<512, 256>>>(ec3_w, u3, 1, 512, 256);
    wtrans_k<<<512, 256>>>(dc0_w, uD0, 1, 256, 512);
    wtrans_k<<<512, 256>>>(dc1_w, uD1, 1, 512, 256);
    wtrans_k<<<4096, 256>>>(er_w1, uE1, 16, 512, 128);
    wtrans_k<<<4096, 256>>>(dr_w1, uDr1, 16, 512, 128);
    pack1x1_k<<<2048, 256>>>(er_w2, pwE2, 16, 128, 512);
    pack1x1_k<<<2048, 256>>>(dr_w2, pwDr2, 16, 128, 512);
    packT_k<<<1024, 256>>>(codebook, cbT);
    init_k<<<128, 256>>>(bestkey, vqsum, reconsum);
    cnorm_k<<<1024, 256>>>(codebook, cn);

    // ---- encoder ----
    conv0_k<<<32768, 256>>>(x, ec0_w, ec0_b, bufZ);
    bn_stats_k<<<256, 256>>>(bufZ, ebn0_g, ebn0_b, 256, bnsc, bnsh);
    bn_apply_k<<<32768, 256>>>(bufZ, bnsc, bnsh, 256, 8 * 256 * 4096);

    // conv1: 256 -> 512
    win_in_k<false><<<8192, 256>>>(bufZ, V, 256);
    win_gemm_k<<<dim3(64, 128), 256>>>(u1, V, M, 256, 512);
    win_out_k<false><<<16384, 256>>>(M, ec1_b, bufA, 512);
    bn_stats_k<<<512, 256>>>(bufA, ebn1_g, ebn1_b, 512, bnsc, bnsh);
    bn_apply_k<<<65536, 256>>>(bufA, bnsc, bnsh, 512, 8 * 512 * 4096);

    // conv2: 512 -> 512
    win_in_k<false><<<16384, 256>>>(bufA, V, 512);
    win_gemm_k<<<dim3(64, 128), 256>>>(u2, V, M, 512, 512);
    win_out_k<false><<<16384, 256>>>(M, ec2_b, bufB, 512);

    // encoder res stacks
    for (int blk = 0; blk < 16; blk++) {
        win_in_k<true><<<16384, 256>>>(bufB, V, 512);
        win_gemm_k<<<dim3(16, 128), 256>>>(uE1 + (size_t)blk * resU, V, M, 512, 128);
        win_out_k<true><<<4096, 256>>>(M, er_b1 + blk * 128, bufT, 128);
        conv1x1_acc_k<<<dim3(4, BH), 256>>>(
            bufT, pwE2 + (size_t)blk * 128 * 512, er_b2 + blk * 512, bufB, 128, 512);
        if ((blk & 3) == 3)
            relu_ip_k<<<65536, 256>>>(bufB, 8 * 512 * 4096);
    }

    // conv3: 512 -> 256
    win_in_k<false><<<16384, 256>>>(bufB, V, 512);
    win_gemm_k<<<dim3(32, 128), 256>>>(u3, V, M, 512, 256);
    win_out_k<false><<<8192, 256>>>(M, ec3_b, bufZ, 256);

    // ---- vector quantizer ----
    znorm_k<<<128, 256>>>(bufZ, zn);
    vq_argmin_k<<<dim3(16, BH), 256>>>(bufZ, cbT, cn, zn, bestkey);
    vq_gather_k<<<32768, 256>>>(bufZ, codebook, bestkey, bufA, vqsum);

    // ---- decoder ----
    // dec conv0: 256 -> 512
    win_in_k<false><<<8192, 256>>>(bufA, V, 256);
    win_gemm_k<<<dim3(64, 128), 256>>>(uD0, V, M, 256, 512);
    win_out_k<false><<<16384, 256>>>(M, dc0_b, bufB, 512);

    for (int blk = 0; blk < 16; blk++) {
        win_in_k<true><<<16384, 256>>>(bufB, V, 512);
        win_gemm_k<<<dim3(16, 128), 256>>>(uDr1 + (size_t)blk * resU, V, M, 512, 128);
        win_out_k<true><<<4096, 256>>>(M, dr_b1 + blk * 128, bufT, 128);
        conv1x1_acc_k<<<dim3(4, BH), 256>>>(
            bufT, pwDr2 + (size_t)blk * 128 * 512, dr_b2 + blk * 512, bufB, 128, 512);
        if ((blk & 3) == 3)
            relu_ip_k<<<65536, 256>>>(bufB, 8 * 512 * 4096);
    }

    // dec conv1: 512 -> 256, relu
    win_in_k<false><<<16384, 256>>>(bufB, V, 512);
    win_gemm_k<<<dim3(32, 128), 256>>>(uD1, V, M, 512, 256);
    win_out_k<true><<<8192, 256>>>(M, dc1_b, bufZ, 256);

    deconv_k<<<1536, 256>>>(bufZ, dd_w, dd_b, x, out, reconsum);
    finalize_k<<<1, 1>>>(out, vqsum, reconsum);
}

// round 7
// speedup vs baseline: 4.5090x; 1.1184x over previous
#include <cuda_runtime.h>
#include <math.h>

// ---------------------------------------------------------------------------
// VQ-VAE forward. x: [8,3,128,128]; encoder spatial 64x64. BH = 8*64 = 512.
// Encoder 3x3 convs: Winograd F(2x2,3x3), 8192 tiles (exactness protects VQ).
// Decoder 3x3 convs: Winograd F(4x4,3x3), 2048 tiles (1.78x fewer FLOPs).
// ---------------------------------------------------------------------------

#define BH 512

// ------------------------------- scratch -----------------------------------
__device__ float g_bufA[16777216];   // [8,512,64,64]
__device__ float g_bufB[16777216];   // [8,512,64,64]
__device__ float g_bufT[4194304];    // [8,128,64,64]
__device__ float g_bufZ[8388608];    // [8,256,64,64]

__device__ float g_V[67108864];      // winograd input  planes
__device__ float g_M[67108864];      // winograd output planes

__device__ float g_u1 [2097152];     // conv1  U [16][256][512]
__device__ float g_u2 [4194304];     // conv2  U [16][512][512]
__device__ float g_u3 [2097152];     // conv3  U [16][512][256]
__device__ float g_uE1[16777216];    // enc res U [16 lay][16][512][128]

__device__ float g_u4D0[4718592];    // dec c0 U4 [36][256][512]
__device__ float g_u4D1[4718592];    // dec c1 U4 [36][512][256]
__device__ float g_u4Dr1[37748736];  // dec res U4 [16 lay][36][512][128]

__device__ float g_pwE2[1048576];    // enc res w2 packed [16][128][512]
__device__ float g_pwDr2[1048576];   // dec res w2 packed

__device__ float g_cbT [262144];     // codebook^T [256][1024]
__device__ float g_cnorm[1024];
__device__ float g_znorm[32768];
__device__ unsigned long long g_bestkey[32768];
__device__ float g_bnscale[512];
__device__ float g_bnshift[512];
__device__ float g_vqsum;
__device__ float g_reconsum;

// ---------------------------- small helpers --------------------------------
__device__ __forceinline__ float warpReduceSum(float v) {
#pragma unroll
    for (int s = 16; s > 0; s >>= 1) v += __shfl_down_sync(0xffffffffu, v, s);
    return v;
}

// ------------------------------ pack kernels -------------------------------
__global__ void pack1x1_k(const float* __restrict__ src, float* __restrict__ dst,
                          int nblk, int Cin, int Cout) {
    long long total = (long long)nblk * Cout * Cin;
    for (long long i = (long long)blockIdx.x * blockDim.x + threadIdx.x; i < total;
         i += (long long)gridDim.x * blockDim.x) {
        int ci = (int)(i % Cin);
        long long t = i / Cin;
        int co = (int)(t % Cout);
        int blk = (int)(t / Cout);
        dst[((long long)blk * Cin + ci) * Cout + co] = src[i];
    }
}

// F(2x2) weight transform: w [nblk][Cout][Cin][3][3] -> U [nblk][16][Cin][Cout]
__global__ void wtrans_k(const float* __restrict__ w, float* __restrict__ U,
                         int nblk, int Cin, int Cout) {
    long long total = (long long)nblk * Cout * Cin;
    long long idx = (long long)blockIdx.x * blockDim.x + threadIdx.x;
    if (idx >= total) return;
    int ci = (int)(idx % Cin);
    long long rest = idx / Cin;
    int co = (int)(rest % Cout);
    int blk = (int)(rest / Cout);
    const float* g = w + idx * 9;
    float gg[3][3];
#pragma unroll
    for (int i = 0; i < 3; i++)
#pragma unroll
        for (int j = 0; j < 3; j++) gg[i][j] = g[i * 3 + j];
    float tu[4][3];
#pragma unroll
    for (int j = 0; j < 3; j++) {
        tu[0][j] = gg[0][j];
        tu[1][j] = 0.5f * (gg[0][j] + gg[1][j] + gg[2][j]);
        tu[2][j] = 0.5f * (gg[0][j] - gg[1][j] + gg[2][j]);
        tu[3][j] = gg[2][j];
    }
#pragma unroll
    for (int i = 0; i < 4; i++) {
        float u0 = tu[i][0];
        float u1 = 0.5f * (tu[i][0] + tu[i][1] + tu[i][2]);
        float u2 = 0.5f * (tu[i][0] - tu[i][1] + tu[i][2]);
        float u3 = tu[i][2];
        size_t base = (((size_t)blk * 16 + i * 4) * Cin + ci) * Cout + co;
        size_t pl = (size_t)Cin * Cout;
        U[base]          = u0;
        U[base + pl]     = u1;
        U[base + 2 * pl] = u2;
        U[base + 3 * pl] = u3;
    }
}

// F(4x4) weight transform: w [nblk][Cout][Cin][3][3] -> U [nblk][36][Cin][Cout]
__global__ void wtrans4_k(const float* __restrict__ w, float* __restrict__ U,
                          int nblk, int Cin, int Cout) {
    long long total = (long long)nblk * Cout * Cin;
    long long idx = (long long)blockIdx.x * blockDim.x + threadIdx.x;
    if (idx >= total) return;
    int ci = (int)(idx % Cin);
    long long rest = idx / Cin;
    int co = (int)(rest % Cout);
    int blk = (int)(rest / Cout);
    const float* g = w + idx * 9;
    float q[6][3];
#pragma unroll
    for (int j = 0; j < 3; j++) {
        float g0 = g[j], g1 = g[3 + j], g2 = g[6 + j];
        q[0][j] = 0.25f * g0;
        q[1][j] = (-g0 - g1 - g2) * (1.f / 6.f);
        q[2][j] = (-g0 + g1 - g2) * (1.f / 6.f);
        q[3][j] = g0 * (1.f / 24.f) + g1 * (1.f / 12.f) + g2 * (1.f / 6.f);
        q[4][j] = g0 * (1.f / 24.f) - g1 * (1.f / 12.f) + g2 * (1.f / 6.f);
        q[5][j] = g2;
    }
    size_t pl = (size_t)Cin * Cout;
    size_t base0 = (((size_t)blk * 36) * Cin + ci) * Cout + co;
#pragma unroll
    for (int i = 0; i < 6; i++) {
        float t0 = q[i][0], t1 = q[i][1], t2 = q[i][2];
        float u[6];
        u[0] = 0.25f * t0;
        u[1] = (-t0 - t1 - t2) * (1.f / 6.f);
        u[2] = (-t0 + t1 - t2) * (1.f / 6.f);
        u[3] = t0 * (1.f / 24.f) + t1 * (1.f / 12.f) + t2 * (1.f / 6.f);
        u[4] = t0 * (1.f / 24.f) - t1 * (1.f / 12.f) + t2 * (1.f / 6.f);
        u[5] = t2;
#pragma unroll
        for (int j = 0; j < 6; j++)
            U[base0 + (size_t)(i * 6 + j) * pl] = u[j];
    }
}

// codebook [1024][256] -> cbT [256][1024]
__global__ void packT_k(const float* __restrict__ src, float* __restrict__ dst) {
    int i = blockIdx.x * blockDim.x + threadIdx.x;
    if (i < 262144) {
        int d = i & 255, k = i >> 8;
        dst[d * 1024 + k] = src[i];
    }
}

__global__ void init_k(unsigned long long* bestkey, float* vqsum, float* reconsum) {
    int i = blockIdx.x * blockDim.x + threadIdx.x;
    if (i < 32768) bestkey[i] = 0xFFFFFFFFFFFFFFFFull;
    if (i == 0) { *vqsum = 0.f; *reconsum = 0.f; }
}

__global__ void cnorm_k(const float* __restrict__ cb, float* __restrict__ cn) {
    int k = blockIdx.x;
    float v = cb[k * 256 + threadIdx.x];
    float p = warpReduceSum(v * v);
    __shared__ float sh[8];
    if ((threadIdx.x & 31) == 0) sh[threadIdx.x >> 5] = p;
    __syncthreads();
    if (threadIdx.x == 0) {
        float t = 0.f;
#pragma unroll
        for (int i = 0; i < 8; i++) t += sh[i];
        cn[k] = t;
    }
}

__global__ void znorm_k(const float* __restrict__ z, float* __restrict__ zn) {
    int n = blockIdx.x * blockDim.x + threadIdx.x;
    if (n >= 32768) return;
    int b = n >> 12, rem = n & 4095;
    const float* zp = z + (((size_t)b * 256) << 12) + rem;
    float s = 0.f;
#pragma unroll 8
    for (int d = 0; d < 256; d++) {
        float v = zp[(size_t)d << 12];
        s = fmaf(v, v, s);
    }
    zn[n] = s;
}

// ------------------------------ conv0 (4x4 s2) ------------------------------
__global__ void conv0_k(const float* __restrict__ x, const float* __restrict__ w,
                        const float* __restrict__ bias, float* __restrict__ out) {
    int idx = blockIdx.x * blockDim.x + threadIdx.x;
    if (idx >= 8388608) return;
    int ox = idx & 63, oy = (idx >> 6) & 63, co = (idx >> 12) & 255, b = idx >> 20;
    float acc = bias[co];
    const float* wc = w + co * 48;
#pragma unroll
    for (int c = 0; c < 3; c++) {
        const float* xp = x + (size_t)(b * 3 + c) * 16384;
#pragma unroll
        for (int ky = 0; ky < 4; ky++) {
            int iy = oy * 2 - 1 + ky;
            if (iy < 0 || iy >= 128) continue;
#pragma unroll
            for (int kx = 0; kx < 4; kx++) {
                int ix = ox * 2 - 1 + kx;
                if (ix < 0 || ix >= 128) continue;
                acc = fmaf(xp[iy * 128 + ix], wc[c * 16 + ky * 4 + kx], acc);
            }
        }
    }
    out[idx] = acc;
}

// ------------------------------- batchnorm ----------------------------------
__global__ void bn_stats_k(const float* __restrict__ buf, const float* __restrict__ g,
                           const float* __restrict__ bb, int C,
                           float* __restrict__ scale, float* __restrict__ shift) {
    int c = blockIdx.x;
    int tid = threadIdx.x;
    double s = 0.0, s2 = 0.0;
    for (int t = tid; t < 8 * 4096; t += 256) {
        int b = t >> 12, off = t & 4095;
        float v = buf[(((size_t)b * C + c) << 12) + off];
        s += (double)v; s2 += (double)v * v;
    }
    __shared__ double sh[256], sh2[256];
    sh[tid] = s; sh2[tid] = s2;
    __syncthreads();
    for (int st = 128; st; st >>= 1) {
        if (tid < st) { sh[tid] += sh[tid + st]; sh2[tid] += sh2[tid + st]; }
        __syncthreads();
    }
    if (tid == 0) {
        double m = sh[0] / 32768.0;
        double v = sh2[0] / 32768.0 - m * m;
        double sc = (double)g[c] / sqrt(v + 1e-5);
        scale[c] = (float)sc;
        shift[c] = (float)((double)bb[c] - m * sc);
    }
}

__global__ void bn_apply_k(float* __restrict__ buf, const float* __restrict__ scale,
                           const float* __restrict__ shift, int C, int total) {
    int i = blockIdx.x * blockDim.x + threadIdx.x;
    if (i >= total) return;
    int c = (i >> 12) % C;
    buf[i] = fmaxf(fmaf(buf[i], scale[c], shift[c]), 0.f);
}

__global__ void relu_ip_k(float* __restrict__ buf, int total) {
    int i = blockIdx.x * blockDim.x + threadIdx.x;
    if (i < total) buf[i] = fmaxf(buf[i], 0.f);
}

// ---------------------- F(2x2): input transform (encoder) -------------------
template <bool RELU>
__global__ void win_in_k(const float* __restrict__ in, float* __restrict__ V, int Cin) {
    int idx = blockIdx.x * 256 + threadIdx.x;      // Cin * 8192
    if (idx >= (Cin << 13)) return;
    int tile = idx & 8191, ci = idx >> 13;
    int b = tile >> 10, t = tile & 1023, ty = t >> 5, tx = t & 31;
    const float* src = in + (((size_t)b * Cin + ci) << 12);
    const int iy0 = 2 * ty - 1, ix0 = 2 * tx - 1;
    float d[4][4];
#pragma unroll
    for (int i = 0; i < 4; i++) {
        int iy = iy0 + i;
        bool yok = (iy >= 0 && iy < 64);
#pragma unroll
        for (int j = 0; j < 4; j++) {
            int ix = ix0 + j;
            float v = (yok && ix >= 0 && ix < 64) ? src[iy * 64 + ix] : 0.f;
            if (RELU) v = fmaxf(v, 0.f);
            d[i][j] = v;
        }
    }
    float tr[4][4];
#pragma unroll
    for (int j = 0; j < 4; j++) {
        tr[0][j] = d[0][j] - d[2][j];
        tr[1][j] = d[1][j] + d[2][j];
        tr[2][j] = d[2][j] - d[1][j];
        tr[3][j] = d[1][j] - d[3][j];
    }
#pragma unroll
    for (int i = 0; i < 4; i++) {
        float v0 = tr[i][0] - tr[i][2];
        float v1 = tr[i][1] + tr[i][2];
        float v2 = tr[i][2] - tr[i][1];
        float v3 = tr[i][1] - tr[i][3];
        size_t base = (((size_t)(i * 4) * 512 + ci) << 13) + tile;
        V[base]                            = v0;
        V[base + ((size_t)512 << 13)]      = v1;
        V[base + (size_t)2 * ((size_t)512 << 13)] = v2;
        V[base + (size_t)3 * ((size_t)512 << 13)] = v3;
    }
}

// ---------------------- F(4x4): input transform (decoder) -------------------
template <bool RELU>
__global__ void win4_in_k(const float* __restrict__ in, float* __restrict__ V, int Cin) {
    int idx = blockIdx.x * 256 + threadIdx.x;      // Cin * 2048
    if (idx >= (Cin << 11)) return;
    int tile = idx & 2047, ci = idx >> 11;
    int b = tile >> 8, t = tile & 255, ty = t >> 4, tx = t & 15;
    const float* src = in + (((size_t)b * Cin + ci) << 12);
    const int iy0 = 4 * ty - 1, ix0 = 4 * tx - 1;
    float d[6][6];
#pragma unroll
    for (int i = 0; i < 6; i++) {
        int iy = iy0 + i;
        bool yok = (iy >= 0 && iy < 64);
#pragma unroll
        for (int j = 0; j < 6; j++) {
            int ix = ix0 + j;
            float v = (yok && ix >= 0 && ix < 64) ? src[iy * 64 + ix] : 0.f;
            if (RELU) v = fmaxf(v, 0.f);
            d[i][j] = v;
        }
    }
    float w[6][6];
#pragma unroll
    for (int j = 0; j < 6; j++) {
        w[0][j] = 4.f * d[0][j] - 5.f * d[2][j] + d[4][j];
        w[1][j] = -4.f * d[1][j] - 4.f * d[2][j] + d[3][j] + d[4][j];
        w[2][j] = 4.f * d[1][j] - 4.f * d[2][j] - d[3][j] + d[4][j];
        w[3][j] = -2.f * d[1][j] - d[2][j] + 2.f * d[3][j] + d[4][j];
        w[4][j] = 2.f * d[1][j] - d[2][j] - 2.f * d[3][j] + d[4][j];
        w[5][j] = 4.f * d[1][j] - 5.f * d[3][j] + d[5][j];
    }
#pragma unroll
    for (int i = 0; i < 6; i++) {
        float v0 = 4.f * w[i][0] - 5.f * w[i][2] + w[i][4];
        float v1 = -4.f * w[i][1] - 4.f * w[i][2] + w[i][3] + w[i][4];
        float v2 = 4.f * w[i][1] - 4.f * w[i][2] - w[i][3] + w[i][4];
        float v3 = -2.f * w[i][1] - w[i][2] + 2.f * w[i][3] + w[i][4];
        float v4 = 2.f * w[i][1] - w[i][2] - 2.f * w[i][3] + w[i][4];
        float v5 = 4.f * w[i][1] - 5.f * w[i][3] + w[i][5];
        size_t pl = (size_t)512 * 2048;
        size_t base = ((size_t)(i * 6) * 512 + ci) * 2048 + tile;
        V[base]          = v0;
        V[base + pl]     = v1;
        V[base + 2 * pl] = v2;
        V[base + 3 * pl] = v3;
        V[base + 4 * pl] = v4;
        V[base + 5 * pl] = v5;
    }
}

// ---------------------- Winograd batched GEMM (scalar FFMA core) ------------
// M[r][co][tile] = sum_ci U[r][ci][co] * V[r][ci][tile]; V ch-stride = ntiles,
// V plane stride = 512*ntiles; M row stride = ntiles.
__global__ void __launch_bounds__(256)
win_gemm_k(const float* __restrict__ U, const float* __restrict__ V,
           float* __restrict__ M, int Cin, int Cout, int ntiles) {
    const int coutTiles = Cout >> 7;
    const int r = blockIdx.x / coutTiles;
    const int co0 = (blockIdx.x % coutTiles) * 128;
    const int tile0 = blockIdx.y * 64;
    const int tid = threadIdx.x;
    const int tx = tid & 15, ty = tid >> 4;

    __shared__ __align__(16) float Ws[16][128];
    __shared__ __align__(16) float Xs[16][64];

    float acc[8][4];
#pragma unroll
    for (int i = 0; i < 8; i++)
#pragma unroll
        for (int j = 0; j < 4; j++) acc[i][j] = 0.f;

    const int l = tid * 4;
    const int kW = l >> 7, coW = l & 127;
    const int kX = l >> 6, pxX = l & 63;

    const float* Ur = U + (size_t)r * Cin * Cout;
    const float* Vr = V + (size_t)r * 512 * ntiles;

    for (int c0 = 0; c0 < Cin; c0 += 16) {
        __syncthreads();
        *(float4*)&Ws[kW][coW] =
            *(const float4*)(Ur + (size_t)(c0 + kW) * Cout + co0 + coW);
        *(float4*)&Ws[kW + 8][coW] =
            *(const float4*)(Ur + (size_t)(c0 + kW + 8) * Cout + co0 + coW);
        *(float4*)&Xs[kX][pxX] =
            *(const float4*)(Vr + (size_t)(c0 + kX) * ntiles + tile0 + pxX);
        __syncthreads();
#pragma unroll
        for (int k = 0; k < 16; k++) {
            const float4 bv = *(const float4*)&Xs[k][tx * 4];
            const float4 a0 = *(const float4*)&Ws[k][ty * 8];
            const float4 a1 = *(const float4*)&Ws[k][ty * 8 + 4];
            const float bj[4] = {bv.x, bv.y, bv.z, bv.w};
            const float ai[8] = {a0.x, a0.y, a0.z, a0.w, a1.x, a1.y, a1.z, a1.w};
#pragma unroll
            for (int i = 0; i < 8; i++)
#pragma unroll
                for (int j = 0; j < 4; j++)
                    acc[i][j] = fmaf(ai[i], bj[j], acc[i][j]);
        }
    }

#pragma unroll
    for (int i = 0; i < 8; i++) {
        const int co = co0 + ty * 8 + i;
        float* orow = M + ((size_t)r * Cout + co) * ntiles + tile0;
        *(float4*)(orow + tx * 4) = make_float4(acc[i][0], acc[i][1], acc[i][2], acc[i][3]);
    }
}

// ---------------------- F(2x2): inverse transform ---------------------------
template <bool RELU>
__global__ void win_out_k(const float* __restrict__ M, const float* __restrict__ bias,
                          float* __restrict__ out, int Cout) {
    int idx = blockIdx.x * 256 + threadIdx.x;      // Cout * 8192
    if (idx >= (Cout << 13)) return;
    int tile = idx & 8191, co = idx >> 13;
    float m[4][4];
#pragma unroll
    for (int i = 0; i < 4; i++)
#pragma unroll
        for (int j = 0; j < 4; j++)
            m[i][j] = M[(((size_t)(i * 4 + j) * Cout + co) << 13) + tile];
    float t0[4], t1[4];
#pragma unroll
    for (int j = 0; j < 4; j++) {
        t0[j] = m[0][j] + m[1][j] + m[2][j];
        t1[j] = m[1][j] - m[2][j] - m[3][j];
    }
    const float bs = bias[co];
    float o00 = t0[0] + t0[1] + t0[2] + bs;
    float o01 = t0[1] - t0[2] - t0[3] + bs;
    float o10 = t1[0] + t1[1] + t1[2] + bs;
    float o11 = t1[1] - t1[2] - t1[3] + bs;
    if (RELU) {
        o00 = fmaxf(o00, 0.f); o01 = fmaxf(o01, 0.f);
        o10 = fmaxf(o10, 0.f); o11 = fmaxf(o11, 0.f);
    }
    int b = tile >> 10, t = tile & 1023, ty = t >> 5, tx = t & 31;
    float* dst = out + (((size_t)b * Cout + co) << 12) + (2 * ty) * 64 + 2 * tx;
    dst[0] = o00; dst[1] = o01;
    dst[64] = o10; dst[65] = o11;
}

// ---------------------- F(4x4): inverse transform ---------------------------
template <bool RELU>
__global__ void win4_out_k(const float* __restrict__ M, const float* __restrict__ bias,
                           float* __restrict__ out, int Cout) {
    int idx = blockIdx.x * 256 + threadIdx.x;      // Cout * 2048
    if (idx >= (Cout << 11)) return;
    int tile = idx & 2047, co = idx >> 11;
    float m[6][6];
#pragma unroll
    for (int i = 0; i < 6; i++)
#pragma unroll
        for (int j = 0; j < 6; j++)
            m[i][j] = M[((size_t)(i * 6 + j) * Cout + co) * 2048 + tile];
    float s[4][6];
#pragma unroll
    for (int j = 0; j < 6; j++) {
        s[0][j] = m[0][j] + m[1][j] + m[2][j] + m[3][j] + m[4][j];
        s[1][j] = m[1][j] - m[2][j] + 2.f * (m[3][j] - m[4][j]);
        s[2][j] = m[1][j] + m[2][j] + 4.f * (m[3][j] + m[4][j]);
        s[3][j] = m[1][j] - m[2][j] + 8.f * (m[3][j] - m[4][j]) + m[5][j];
    }
    const float bs = bias[co];
    int b = tile >> 8, t = tile & 255, ty = t >> 4, tx = t & 15;
    float* dst0 = out + (((size_t)b * Cout + co) << 12) + (4 * ty) * 64 + 4 * tx;
#pragma unroll
    for (int i = 0; i < 4; i++) {
        float y0 = s[i][0] + s[i][1] + s[i][2] + s[i][3] + s[i][4] + bs;
        float y1 = s[i][1] - s[i][2] + 2.f * (s[i][3] - s[i][4]) + bs;
        float y2 = s[i][1] + s[i][2] + 4.f * (s[i][3] + s[i][4]) + bs;
        float y3 = s[i][1] - s[i][2] + 8.f * (s[i][3] - s[i][4]) + s[i][5] + bs;
        if (RELU) {
            y0 = fmaxf(y0, 0.f); y1 = fmaxf(y1, 0.f);
            y2 = fmaxf(y2, 0.f); y3 = fmaxf(y3, 0.f);
        }
        float* dst = dst0 + i * 64;
        dst[0] = y0; dst[1] = y1; dst[2] = y2; dst[3] = y3;
    }
}

// --------------------- 1x1 conv + residual add (scalar) ----------------------
__global__ void __launch_bounds__(256)
conv1x1_acc_k(const float* __restrict__ in, const float* __restrict__ wp,
              const float* __restrict__ bias, float* __restrict__ out,
              int Cin, int Cout) {
    const int cout0 = blockIdx.x * 128;
    const int by = blockIdx.y;
    const int b = by >> 6, y = by & 63;
    const int tid = threadIdx.x;
    const int tx = tid & 15, ty = tid >> 4;

    __shared__ __align__(16) float Ws[16][128];
    __shared__ __align__(16) float Xs[16][64];

    float acc[8][4];
#pragma unroll
    for (int i = 0; i < 8; i++)
#pragma unroll
        for (int j = 0; j < 4; j++) acc[i][j] = 0.f;

    const int l = tid * 4;
    const int kW = l >> 7, coW = l & 127;
    const int kX = l >> 6, pxX = l & 63;
    const float* inrow = in + (size_t)b * Cin * 4096 + (size_t)y * 64;

    for (int c0 = 0; c0 < Cin; c0 += 16) {
        __syncthreads();
        *(float4*)&Ws[kW][coW] =
            *(const float4*)(wp + (size_t)(c0 + kW) * Cout + cout0 + coW);
        *(float4*)&Ws[kW + 8][coW] =
            *(const float4*)(wp + (size_t)(c0 + kW + 8) * Cout + cout0 + coW);
        *(float4*)&Xs[kX][pxX] =
            *(const float4*)(inrow + (size_t)(c0 + kX) * 4096 + pxX);
        __syncthreads();
#pragma unroll
        for (int k = 0; k < 16; k++) {
            const float4 bv = *(const float4*)&Xs[k][tx * 4];
            const float4 a0 = *(const float4*)&Ws[k][ty * 8];
            const float4 a1 = *(const float4*)&Ws[k][ty * 8 + 4];
            const float bj[4] = {bv.x, bv.y, bv.z, bv.w};
            const float ai[8] = {a0.x, a0.y, a0.z, a0.w, a1.x, a1.y, a1.z, a1.w};
#pragma unroll
            for (int i = 0; i < 8; i++)
#pragma unroll
                for (int j = 0; j < 4; j++)
                    acc[i][j] = fmaf(ai[i], bj[j], acc[i][j]);
        }
    }

#pragma unroll
    for (int i = 0; i < 8; i++) {
        const int co = cout0 + ty * 8 + i;
        const float bs = bias[co];
        float* orow = out + (((size_t)b * Cout + co) * 64 + y) * 64;
        float4 cur = *(float4*)(orow + tx * 4);
        cur.x += acc[i][0] + bs; cur.y += acc[i][1] + bs;
        cur.z += acc[i][2] + bs; cur.w += acc[i][3] + bs;
        *(float4*)(orow + tx * 4) = cur;
    }
}

// ------------------------------- VQ argmin -----------------------------------
__global__ void __launch_bounds__(256)
vq_argmin_k(const float* __restrict__ z, const float* __restrict__ cbT,
            const float* __restrict__ cn, const float* __restrict__ zn,
            unsigned long long* __restrict__ bestkey) {
    const int code0 = blockIdx.x * 64;
    const int by = blockIdx.y;
    const int b = by >> 6, y = by & 63;
    const int tid = threadIdx.x;
    const int tx = tid & 15, ty = tid >> 4;

    __shared__ __align__(16) float Cs[16][64];
    __shared__ __align__(16) float Zs[16][64];
    __shared__ unsigned long long red[16][64];

    float acc[4][4];
#pragma unroll
    for (int i = 0; i < 4; i++)
#pragma unroll
        for (int j = 0; j < 4; j++) acc[i][j] = 0.f;

    const int l = tid * 4;
    const int k = l >> 6, c = l & 63;

    for (int d0 = 0; d0 < 256; d0 += 16) {
        __syncthreads();
        *(float4*)&Cs[k][c] = *(const float4*)&cbT[(size_t)(d0 + k) * 1024 + code0 + c];
        *(float4*)&Zs[k][c] =
            *(const float4*)&z[(((size_t)b * 256 + d0 + k) * 64 + y) * 64 + c];
        __syncthreads();
#pragma unroll
        for (int kk = 0; kk < 16; kk++) {
            const float4 av = *(const float4*)&Cs[kk][ty * 4];
            const float4 bv = *(const float4*)&Zs[kk][tx * 4];
            const float ai[4] = {av.x, av.y, av.z, av.w};
            const float bj[4] = {bv.x, bv.y, bv.z, bv.w};
#pragma unroll
            for (int i = 0; i < 4; i++)
#pragma unroll
                for (int j = 0; j < 4; j++)
                    acc[i][j] = fmaf(ai[i], bj[j], acc[i][j]);
        }
    }

#pragma unroll
    for (int j = 0; j < 4; j++) {
        const float znv = zn[by * 64 + tx * 4 + j];
        unsigned long long best = 0xFFFFFFFFFFFFFFFFull;
#pragma unroll
        for (int i = 0; i < 4; i++) {
            const int code = code0 + ty * 4 + i;
            const float s = (znv - 2.f * acc[i][j]) + cn[code];
            unsigned int u = __float_as_uint(s);
            unsigned int k32 = (u >> 31) ? ~u : (u | 0x80000000u);
            unsigned long long key = ((unsigned long long)k32 << 32) | (unsigned int)code;
            best = (key < best) ? key : best;
        }
        red[ty][tx * 4 + j] = best;
    }
    __syncthreads();
    for (int st = 8; st; st >>= 1) {
        if (ty < st) {
#pragma unroll
            for (int j = 0; j < 4; j++) {
                unsigned long long a = red[ty][tx * 4 + j];
                unsigned long long b2 = red[ty + st][tx * 4 + j];
                red[ty][tx * 4 + j] = (b2 < a) ? b2 : a;
            }
        }
        __syncthreads();
    }
    if (ty == 0) {
#pragma unroll
        for (int j = 0; j < 4; j++)
            atomicMin(&bestkey[by * 64 + tx * 4 + j], red[0][tx * 4 + j]);
    }
}

__global__ void vq_gather_k(const float* __restrict__ z, const float* __restrict__ cb,
                            const unsigned long long* __restrict__ bestkey,
                            float* __restrict__ zq, float* __restrict__ vqsum) {
    const int n = blockIdx.x;
    const int d = threadIdx.x;
    const int idx = (int)(bestkey[n] & 0xFFFFFFFFull);
    const int b = n >> 12, rem = n & 4095;
    const float q = cb[idx * 256 + d];
    const size_t zoff = (((size_t)b * 256 + d) << 12) + rem;
    const float zv = z[zoff];
    const float diff = q - zv;
    zq[zoff] = zv + diff;
    float p = warpReduceSum(diff * diff);
    __shared__ float sh[8];
    if ((threadIdx.x & 31) == 0) sh[threadIdx.x >> 5] = p;
    __syncthreads();
    if (threadIdx.x == 0) {
        float t = 0.f;
#pragma unroll
        for (int i = 0; i < 8; i++) t += sh[i];
        atomicAdd(vqsum, t);
    }
}

// -------------------------------- deconv -------------------------------------
__global__ void deconv_k(const float* __restrict__ in, const float* __restrict__ w,
                         const float* __restrict__ bias, const float* __restrict__ x,
                         float* __restrict__ out, float* __restrict__ reconsum) {
    const int idx = blockIdx.x * blockDim.x + threadIdx.x;
    if (idx >= 393216) return;
    const int ox = idx & 127, oy = (idx >> 7) & 127;
    const int bo = idx >> 14;
    const int o = bo % 3, b = bo / 3;
    float acc = bias[o];
    const int kyp = (oy + 1) & 1, kxp = (ox + 1) & 1;
#pragma unroll
    for (int t = 0; t < 4; t++) {
        const int ky = kyp + 2 * (t >> 1);
        const int kx = kxp + 2 * (t & 1);
        const int ny = oy + 1 - ky, nx = ox + 1 - kx;
        if (ny < 0 || nx < 0) continue;
        const int iy = ny >> 1, ix = nx >> 1;
        if (iy >= 64 || ix >= 64) continue;
        const float* ip = in + (size_t)b * 256 * 4096 + iy * 64 + ix;
        const float* wpp = w + o * 16 + ky * 4 + kx;
        float a = 0.f;
        for (int c2 = 0; c2 < 256; c2++)
            a = fmaf(ip[(size_t)c2 * 4096], wpp[c2 * 48], a);
        acc += a;
    }
    out[idx] = acc;
    const float d = acc - x[idx];
    float p = warpReduceSum(d * d);
    if ((threadIdx.x & 31) == 0) atomicAdd(reconsum, p);
}

__global__ void finalize_k(float* __restrict__ out, const float* __restrict__ vqsum,
                           const float* __restrict__ reconsum) {
    const float recon = *reconsum * (1.f / 393216.f);
    const float vq = 1.25f * (*vqsum) * (1.f / 8388608.f);
    out[393216] = recon + vq;
    out[393217] = recon;
}

// --------------------------------- launch ------------------------------------
extern "C" void kernel_launch(void* const* d_in, const int* in_sizes, int n_in,
                              void* d_out, int out_size) {
    const float* x          = (const float*)d_in[0];
    const float* ec0_w      = (const float*)d_in[1];
    const float* ec0_b      = (const float*)d_in[2];
    const float* ebn0_g     = (const float*)d_in[3];
    const float* ebn0_b     = (const float*)d_in[4];
    const float* ec1_w      = (const float*)d_in[5];
    const float* ec1_b      = (const float*)d_in[6];
    const float* ebn1_g     = (const float*)d_in[7];
    const float* ebn1_b     = (const float*)d_in[8];
    const float* ec2_w      = (const float*)d_in[9];
    const float* ec2_b      = (const float*)d_in[10];
    const float* er_w1      = (const float*)d_in[11];
    const float* er_b1      = (const float*)d_in[12];
    const float* er_w2      = (const float*)d_in[13];
    const float* er_b2      = (const float*)d_in[14];
    const float* ec3_w      = (const float*)d_in[15];
    const float* ec3_b      = (const float*)d_in[16];
    const float* codebook   = (const float*)d_in[17];
    const float* dc0_w      = (const float*)d_in[18];
    const float* dc0_b      = (const float*)d_in[19];
    const float* dr_w1      = (const float*)d_in[20];
    const float* dr_b1      = (const float*)d_in[21];
    const float* dr_w2      = (const float*)d_in[22];
    const float* dr_b2      = (const float*)d_in[23];
    const float* dc1_w      = (const float*)d_in[24];
    const float* dc1_b      = (const float*)d_in[25];
    const float* dd_w       = (const float*)d_in[26];
    const float* dd_b       = (const float*)d_in[27];
    float* out = (float*)d_out;

    float *bufA, *bufB, *bufT, *bufZ, *V, *M;
    float *u1, *u2, *u3, *uE1, *u4D0, *u4D1, *u4Dr1, *pwE2, *pwDr2;
    float *cbT, *cn, *zn, *bnsc, *bnsh, *vqsum, *reconsum;
    unsigned long long* bestkey;
    cudaGetSymbolAddress((void**)&bufA, g_bufA);
    cudaGetSymbolAddress((void**)&bufB, g_bufB);
    cudaGetSymbolAddress((void**)&bufT, g_bufT);
    cudaGetSymbolAddress((void**)&bufZ, g_bufZ);
    cudaGetSymbolAddress((void**)&V,    g_V);
    cudaGetSymbolAddress((void**)&M,    g_M);
    cudaGetSymbolAddress((void**)&u1,   g_u1);
    cudaGetSymbolAddress((void**)&u2,   g_u2);
    cudaGetSymbolAddress((void**)&u3,   g_u3);
    cudaGetSymbolAddress((void**)&uE1,  g_uE1);
    cudaGetSymbolAddress((void**)&u4D0, g_u4D0);
    cudaGetSymbolAddress((void**)&u4D1, g_u4D1);
    cudaGetSymbolAddress((void**)&u4Dr1, g_u4Dr1);
    cudaGetSymbolAddress((void**)&pwE2, g_pwE2);
    cudaGetSymbolAddress((void**)&pwDr2, g_pwDr2);
    cudaGetSymbolAddress((void**)&cbT,  g_cbT);
    cudaGetSymbolAddress((void**)&cn,   g_cnorm);
    cudaGetSymbolAddress((void**)&zn,   g_znorm);
    cudaGetSymbolAddress((void**)&bnsc, g_bnscale);
    cudaGetSymbolAddress((void**)&bnsh, g_bnshift);
    cudaGetSymbolAddress((void**)&vqsum, g_vqsum);
    cudaGetSymbolAddress((void**)&reconsum, g_reconsum);
    cudaGetSymbolAddress((void**)&bestkey, g_bestkey);

    const size_t resU  = (size_t)16 * 512 * 128;   // per enc res layer (F2)
    const size_t resU4 = (size_t)36 * 512 * 128;   // per dec res layer (F4)

    // ---- weight transforms + packs + init ----
    wtrans_k<<<512, 256>>>(ec1_w, u1, 1, 256, 512);
    wtrans_k<<<1024, 256>>>(ec2_w, u2, 1, 512, 512);
    wtrans_k<<<512, 256>>>(ec3_w, u3, 1, 512, 256);
    wtrans_k<<<4096, 256>>>(er_w1, uE1, 16, 512, 128);
    wtrans4_k<<<512, 256>>>(dc0_w, u4D0, 1, 256, 512);
    wtrans4_k<<<512, 256>>>(dc1_w, u4D1, 1, 512, 256);
    wtrans4_k<<<4096, 256>>>(dr_w1, u4Dr1, 16, 512, 128);
    pack1x1_k<<<2048, 256>>>(er_w2, pwE2, 16, 128, 512);
    pack1x1_k<<<2048, 256>>>(dr_w2, pwDr2, 16, 128, 512);
    packT_k<<<1024, 256>>>(codebook, cbT);
    init_k<<<128, 256>>>(bestkey, vqsum, reconsum);
    cnorm_k<<<1024, 256>>>(codebook, cn);

    // ---- encoder (F2x2 — exact path protecting VQ) ----
    conv0_k<<<32768, 256>>>(x, ec0_w, ec0_b, bufZ);
    bn_stats_k<<<256, 256>>>(bufZ, ebn0_g, ebn0_b, 256, bnsc, bnsh);
    bn_apply_k<<<32768, 256>>>(bufZ, bnsc, bnsh, 256, 8 * 256 * 4096);

    win_in_k<false><<<8192, 256>>>(bufZ, V, 256);
    win_gemm_k<<<dim3(64, 128), 256>>>(u1, V, M, 256, 512, 8192);
    win_out_k<false><<<16384, 256>>>(M, ec1_b, bufA, 512);
    bn_stats_k<<<512, 256>>>(bufA, ebn1_g, ebn1_b, 512, bnsc, bnsh);
    bn_apply_k<<<65536, 256>>>(bufA, bnsc, bnsh, 512, 8 * 512 * 4096);

    win_in_k<false><<<16384, 256>>>(bufA, V, 512);
    win_gemm_k<<<dim3(64, 128), 256>>>(u2, V, M, 512, 512, 8192);
    win_out_k<false><<<16384, 256>>>(M, ec2_b, bufB, 512);

    for (int blk = 0; blk < 16; blk++) {
        win_in_k<true><<<16384, 256>>>(bufB, V, 512);
        win_gemm_k<<<dim3(16, 128), 256>>>(uE1 + (size_t)blk * resU, V, M, 512, 128, 8192);
        win_out_k<true><<<4096, 256>>>(M, er_b1 + blk * 128, bufT, 128);
        conv1x1_acc_k<<<dim3(4, BH), 256>>>(
            bufT, pwE2 + (size_t)blk * 128 * 512, er_b2 + blk * 512, bufB, 128, 512);
        if ((blk & 3) == 3)
            relu_ip_k<<<65536, 256>>>(bufB, 8 * 512 * 4096);
    }

    win_in_k<false><<<16384, 256>>>(bufB, V, 512);
    win_gemm_k<<<dim3(32, 128), 256>>>(u3, V, M, 512, 256, 8192);
    win_out_k<false><<<8192, 256>>>(M, ec3_b, bufZ, 256);

    // ---- vector quantizer ----
    znorm_k<<<128, 256>>>(bufZ, zn);
    vq_argmin_k<<<dim3(16, BH), 256>>>(bufZ, cbT, cn, zn, bestkey);
    vq_gather_k<<<32768, 256>>>(bufZ, codebook, bestkey, bufA, vqsum);

    // ---- decoder (F4x4 — 1.78x fewer GEMM FLOPs) ----
    win4_in_k<false><<<2048, 256>>>(bufA, V, 256);
    win_gemm_k<<<dim3(144, 32), 256>>>(u4D0, V, M, 256, 512, 2048);
    win4_out_k<false><<<4096, 256>>>(M, dc0_b, bufB, 512);

    for (int blk = 0; blk < 16; blk++) {
        win4_in_k<true><<<4096, 256>>>(bufB, V, 512);
        win_gemm_k<<<dim3(36, 32), 256>>>(u4Dr1 + (size_t)blk * resU4, V, M, 512, 128, 2048);
        win4_out_k<true><<<1024, 256>>>(M, dr_b1 + blk * 128, bufT, 128);
        conv1x1_acc_k<<<dim3(4, BH), 256>>>(
            bufT, pwDr2 + (size_t)blk * 128 * 512, dr_b2 + blk * 512, bufB, 128, 512);
        if ((blk & 3) == 3)
            relu_ip_k<<<65536, 256>>>(bufB, 8 * 512 * 4096);
    }

    win4_in_k<false><<<4096, 256>>>(bufB, V, 512);
    win_gemm_k<<<dim3(72, 32), 256>>>(u4D1, V, M, 512, 256, 2048);
    win4_out_k<true><<<2048, 256>>>(M, dc1_b, bufZ, 256);

    deconv_k<<<1536, 256>>>(bufZ, dd_w, dd_b, x, out, reconsum);
    finalize_k<<<1, 1>>>(out, vqsum, reconsum);
}

// round 11
// speedup vs baseline: 5.5350x; 1.2275x over previous
#include <cuda_runtime.h>
#include <math.h>

// ---------------------------------------------------------------------------
// VQ-VAE forward. x: [8,3,128,128]; encoder spatial 64x64. BH = 8*64 = 512.
// ALL 3x3 convs run as Winograd F(4x4,3x3): 16x16=256 tiles/image, 2048 total.
// ---------------------------------------------------------------------------

#define BH 512
#define NT4 2048   // 8 images * 16*16 tiles (F4)

// ------------------------------- scratch -----------------------------------
__device__ float g_bufA[16777216];   // [8,512,64,64]
__device__ float g_bufB[16777216];   // [8,512,64,64]
__device__ float g_bufT[4194304];    // [8,128,64,64]
__device__ float g_bufZ[8388608];    // [8,256,64,64]

__device__ float g_V[37748736];      // winograd input  [36][512][2048]
__device__ float g_M[37748736];      // winograd output [36][Cout][2048]

__device__ float g_u4_1 [4718592];   // conv1  U4 [36][256][512]
__device__ float g_u4_2 [9437184];   // conv2  U4 [36][512][512]
__device__ float g_u4_3 [4718592];   // conv3  U4 [36][512][256]
__device__ float g_u4E1 [37748736];  // enc res U4 [16 lay][36][512][128]
__device__ float g_u4D0 [4718592];   // dec c0 U4 [36][256][512]
__device__ float g_u4D1 [4718592];   // dec c1 U4 [36][512][256]
__device__ float g_u4Dr1[37748736];  // dec res U4 [16 lay][36][512][128]

__device__ float g_pwE2[1048576];    // enc res w2 packed [16][128][512]
__device__ float g_pwDr2[1048576];   // dec res w2 packed

__device__ float g_cbT [262144];     // codebook^T [256][1024]
__device__ float g_cnorm[1024];
__device__ float g_znorm[32768];
__device__ unsigned long long g_bestkey[32768];
__device__ float g_bnscale[512];
__device__ float g_bnshift[512];
__device__ float g_vqsum;
__device__ float g_reconsum;

// ---------------------------- small helpers --------------------------------
__device__ __forceinline__ float warpReduceSum(float v) {
#pragma unroll
    for (int s = 16; s > 0; s >>= 1) v += __shfl_down_sync(0xffffffffu, v, s);
    return v;
}

// ------------------------------ pack kernels -------------------------------
__global__ void pack1x1_k(const float* __restrict__ src, float* __restrict__ dst,
                          int nblk, int Cin, int Cout) {
    long long total = (long long)nblk * Cout * Cin;
    for (long long i = (long long)blockIdx.x * blockDim.x + threadIdx.x; i < total;
         i += (long long)gridDim.x * blockDim.x) {
        int ci = (int)(i % Cin);
        long long t = i / Cin;
        int co = (int)(t % Cout);
        int blk = (int)(t / Cout);
        dst[((long long)blk * Cin + ci) * Cout + co] = src[i];
    }
}

// F(4x4) weight transform: w [nblk][Cout][Cin][3][3] -> U [nblk][36][Cin][Cout]
__global__ void wtrans4_k(const float* __restrict__ w, float* __restrict__ U,
                          int nblk, int Cin, int Cout) {
    long long total = (long long)nblk * Cout * Cin;
    long long idx = (long long)blockIdx.x * blockDim.x + threadIdx.x;
    if (idx >= total) return;
    int ci = (int)(idx % Cin);
    long long rest = idx / Cin;
    int co = (int)(rest % Cout);
    int blk = (int)(rest / Cout);
    const float* g = w + idx * 9;
    float q[6][3];
#pragma unroll
    for (int j = 0; j < 3; j++) {
        float g0 = g[j], g1 = g[3 + j], g2 = g[6 + j];
        q[0][j] = 0.25f * g0;
        q[1][j] = (-g0 - g1 - g2) * (1.f / 6.f);
        q[2][j] = (-g0 + g1 - g2) * (1.f / 6.f);
        q[3][j] = g0 * (1.f / 24.f) + g1 * (1.f / 12.f) + g2 * (1.f / 6.f);
        q[4][j] = g0 * (1.f / 24.f) - g1 * (1.f / 12.f) + g2 * (1.f / 6.f);
        q[5][j] = g2;
    }
    size_t pl = (size_t)Cin * Cout;
    size_t base0 = (((size_t)blk * 36) * Cin + ci) * Cout + co;
#pragma unroll
    for (int i = 0; i < 6; i++) {
        float t0 = q[i][0], t1 = q[i][1], t2 = q[i][2];
        float u[6];
        u[0] = 0.25f * t0;
        u[1] = (-t0 - t1 - t2) * (1.f / 6.f);
        u[2] = (-t0 + t1 - t2) * (1.f / 6.f);
        u[3] = t0 * (1.f / 24.f) + t1 * (1.f / 12.f) + t2 * (1.f / 6.f);
        u[4] = t0 * (1.f / 24.f) - t1 * (1.f / 12.f) + t2 * (1.f / 6.f);
        u[5] = t2;
#pragma unroll
        for (int j = 0; j < 6; j++)
            U[base0 + (size_t)(i * 6 + j) * pl] = u[j];
    }
}

// codebook [1024][256] -> cbT [256][1024]
__global__ void packT_k(const float* __restrict__ src, float* __restrict__ dst) {
    int i = blockIdx.x * blockDim.x + threadIdx.x;
    if (i < 262144) {
        int d = i & 255, k = i >> 8;
        dst[d * 1024 + k] = src[i];
    }
}

__global__ void init_k(unsigned long long* bestkey, float* vqsum, float* reconsum) {
    int i = blockIdx.x * blockDim.x + threadIdx.x;
    if (i < 32768) bestkey[i] = 0xFFFFFFFFFFFFFFFFull;
    if (i == 0) { *vqsum = 0.f; *reconsum = 0.f; }
}

__global__ void cnorm_k(const float* __restrict__ cb, float* __restrict__ cn) {
    int k = blockIdx.x;
    float v = cb[k * 256 + threadIdx.x];
    float p = warpReduceSum(v * v);
    __shared__ float sh[8];
    if ((threadIdx.x & 31) == 0) sh[threadIdx.x >> 5] = p;
    __syncthreads();
    if (threadIdx.x == 0) {
        float t = 0.f;
#pragma unroll
        for (int i = 0; i < 8; i++) t += sh[i];
        cn[k] = t;
    }
}

__global__ void znorm_k(const float* __restrict__ z, float* __restrict__ zn) {
    int n = blockIdx.x * blockDim.x + threadIdx.x;
    if (n >= 32768) return;
    int b = n >> 12, rem = n & 4095;
    const float* zp = z + (((size_t)b * 256) << 12) + rem;
    float s = 0.f;
#pragma unroll 8
    for (int d = 0; d < 256; d++) {
        float v = zp[(size_t)d << 12];
        s = fmaf(v, v, s);
    }
    zn[n] = s;
}

// ------------------------------ conv0 (4x4 s2) ------------------------------
__global__ void conv0_k(const float* __restrict__ x, const float* __restrict__ w,
                        const float* __restrict__ bias, float* __restrict__ out) {
    int idx = blockIdx.x * blockDim.x + threadIdx.x;
    if (idx >= 8388608) return;
    int ox = idx & 63, oy = (idx >> 6) & 63, co = (idx >> 12) & 255, b = idx >> 20;
    float acc = bias[co];
    const float* wc = w + co * 48;
#pragma unroll
    for (int c = 0; c < 3; c++) {
        const float* xp = x + (size_t)(b * 3 + c) * 16384;
#pragma unroll
        for (int ky = 0; ky < 4; ky++) {
            int iy = oy * 2 - 1 + ky;
            if (iy < 0 || iy >= 128) continue;
#pragma unroll
            for (int kx = 0; kx < 4; kx++) {
                int ix = ox * 2 - 1 + kx;
                if (ix < 0 || ix >= 128) continue;
                acc = fmaf(xp[iy * 128 + ix], wc[c * 16 + ky * 4 + kx], acc);
            }
        }
    }
    out[idx] = acc;
}

// ------------------------------- batchnorm ----------------------------------
__global__ void bn_stats_k(const float* __restrict__ buf, const float* __restrict__ g,
                           const float* __restrict__ bb, int C,
                           float* __restrict__ scale, float* __restrict__ shift) {
    int c = blockIdx.x;
    int tid = threadIdx.x;
    double s = 0.0, s2 = 0.0;
    for (int t = tid; t < 8 * 4096; t += 256) {
        int b = t >> 12, off = t & 4095;
        float v = buf[(((size_t)b * C + c) << 12) + off];
        s += (double)v; s2 += (double)v * v;
    }
    __shared__ double sh[256], sh2[256];
    sh[tid] = s; sh2[tid] = s2;
    __syncthreads();
    for (int st = 128; st; st >>= 1) {
        if (tid < st) { sh[tid] += sh[tid + st]; sh2[tid] += sh2[tid + st]; }
        __syncthreads();
    }
    if (tid == 0) {
        double m = sh[0] / 32768.0;
        double v = sh2[0] / 32768.0 - m * m;
        double sc = (double)g[c] / sqrt(v + 1e-5);
        scale[c] = (float)sc;
        shift[c] = (float)((double)bb[c] - m * sc);
    }
}

__global__ void bn_apply_k(float* __restrict__ buf, const float* __restrict__ scale,
                           const float* __restrict__ shift, int C, int total) {
    int i = blockIdx.x * blockDim.x + threadIdx.x;
    if (i >= total) return;
    int c = (i >> 12) % C;
    buf[i] = fmaxf(fmaf(buf[i], scale[c], shift[c]), 0.f);
}

__global__ void relu_ip_k(float* __restrict__ buf, int total) {
    int i = blockIdx.x * blockDim.x + threadIdx.x;
    if (i < total) buf[i] = fmaxf(buf[i], 0.f);
}

// ---------------------- F(4x4): input transform -----------------------------
template <bool RELU>
__global__ void win4_in_k(const float* __restrict__ in, float* __restrict__ V, int Cin) {
    int idx = blockIdx.x * 256 + threadIdx.x;      // Cin * 2048
    if (idx >= (Cin << 11)) return;
    int tile = idx & 2047, ci = idx >> 11;
    int b = tile >> 8, t = tile & 255, ty = t >> 4, tx = t & 15;
    const float* src = in + (((size_t)b * Cin + ci) << 12);
    const int iy0 = 4 * ty - 1, ix0 = 4 * tx - 1;
    float d[6][6];
#pragma unroll
    for (int i = 0; i < 6; i++) {
        int iy = iy0 + i;
        bool yok = (iy >= 0 && iy < 64);
#pragma unroll
        for (int j = 0; j < 6; j++) {
            int ix = ix0 + j;
            float v = (yok && ix >= 0 && ix < 64) ? src[iy * 64 + ix] : 0.f;
            if (RELU) v = fmaxf(v, 0.f);
            d[i][j] = v;
        }
    }
    float w[6][6];
#pragma unroll
    for (int j = 0; j < 6; j++) {
        w[0][j] = 4.f * d[0][j] - 5.f * d[2][j] + d[4][j];
        w[1][j] = -4.f * d[1][j] - 4.f * d[2][j] + d[3][j] + d[4][j];
        w[2][j] = 4.f * d[1][j] - 4.f * d[2][j] - d[3][j] + d[4][j];
        w[3][j] = -2.f * d[1][j] - d[2][j] + 2.f * d[3][j] + d[4][j];
        w[4][j] = 2.f * d[1][j] - d[2][j] - 2.f * d[3][j] + d[4][j];
        w[5][j] = 4.f * d[1][j] - 5.f * d[3][j] + d[5][j];
    }
#pragma unroll
    for (int i = 0; i < 6; i++) {
        float v0 = 4.f * w[i][0] - 5.f * w[i][2] + w[i][4];
        float v1 = -4.f * w[i][1] - 4.f * w[i][2] + w[i][3] + w[i][4];
        float v2 = 4.f * w[i][1] - 4.f * w[i][2] - w[i][3] + w[i][4];
        float v3 = -2.f * w[i][1] - w[i][2] + 2.f * w[i][3] + w[i][4];
        float v4 = 2.f * w[i][1] - w[i][2] - 2.f * w[i][3] + w[i][4];
        float v5 = 4.f * w[i][1] - 5.f * w[i][3] + w[i][5];
        size_t pl = (size_t)512 * 2048;
        size_t base = ((size_t)(i * 6) * 512 + ci) * 2048 + tile;
        V[base]          = v0;
        V[base + pl]     = v1;
        V[base + 2 * pl] = v2;
        V[base + 3 * pl] = v3;
        V[base + 4 * pl] = v4;
        V[base + 5 * pl] = v5;
    }
}

// ---------------------- Winograd batched GEMM (scalar FFMA core) ------------
// M[r][co][tile] = sum_ci U[r][ci][co] * V[r][ci][tile]
__global__ void __launch_bounds__(256)
win_gemm_k(const float* __restrict__ U, const float* __restrict__ V,
           float* __restrict__ M, int Cin, int Cout, int ntiles) {
    const int coutTiles = Cout >> 7;
    const int r = blockIdx.x / coutTiles;
    const int co0 = (blockIdx.x % coutTiles) * 128;
    const int tile0 = blockIdx.y * 64;
    const int tid = threadIdx.x;
    const int tx = tid & 15, ty = tid >> 4;

    __shared__ __align__(16) float Ws[16][128];
    __shared__ __align__(16) float Xs[16][64];

    float acc[8][4];
#pragma unroll
    for (int i = 0; i < 8; i++)
#pragma unroll
        for (int j = 0; j < 4; j++) acc[i][j] = 0.f;

    const int l = tid * 4;
    const int kW = l >> 7, coW = l & 127;
    const int kX = l >> 6, pxX = l & 63;

    const float* Ur = U + (size_t)r * Cin * Cout;
    const float* Vr = V + (size_t)r * 512 * ntiles;

    for (int c0 = 0; c0 < Cin; c0 += 16) {
        __syncthreads();
        *(float4*)&Ws[kW][coW] =
            *(const float4*)(Ur + (size_t)(c0 + kW) * Cout + co0 + coW);
        *(float4*)&Ws[kW + 8][coW] =
            *(const float4*)(Ur + (size_t)(c0 + kW + 8) * Cout + co0 + coW);
        *(float4*)&Xs[kX][pxX] =
            *(const float4*)(Vr + (size_t)(c0 + kX) * ntiles + tile0 + pxX);
        __syncthreads();
#pragma unroll
        for (int k = 0; k < 16; k++) {
            const float4 bv = *(const float4*)&Xs[k][tx * 4];
            const float4 a0 = *(const float4*)&Ws[k][ty * 8];
            const float4 a1 = *(const float4*)&Ws[k][ty * 8 + 4];
            const float bj[4] = {bv.x, bv.y, bv.z, bv.w};
            const float ai[8] = {a0.x, a0.y, a0.z, a0.w, a1.x, a1.y, a1.z, a1.w};
#pragma unroll
            for (int i = 0; i < 8; i++)
#pragma unroll
                for (int j = 0; j < 4; j++)
                    acc[i][j] = fmaf(ai[i], bj[j], acc[i][j]);
        }
    }

#pragma unroll
    for (int i = 0; i < 8; i++) {
        const int co = co0 + ty * 8 + i;
        float* orow = M + ((size_t)r * Cout + co) * ntiles + tile0;
        *(float4*)(orow + tx * 4) = make_float4(acc[i][0], acc[i][1], acc[i][2], acc[i][3]);
    }
}

// ---------------------- F(4x4): inverse transform ---------------------------
template <bool RELU>
__global__ void win4_out_k(const float* __restrict__ M, const float* __restrict__ bias,
                           float* __restrict__ out, int Cout) {
    int idx = blockIdx.x * 256 + threadIdx.x;      // Cout * 2048
    if (idx >= (Cout << 11)) return;
    int tile = idx & 2047, co = idx >> 11;
    float m[6][6];
#pragma unroll
    for (int i = 0; i < 6; i++)
#pragma unroll
        for (int j = 0; j < 6; j++)
            m[i][j] = M[((size_t)(i * 6 + j) * Cout + co) * 2048 + tile];
    float s[4][6];
#pragma unroll
    for (int j = 0; j < 6; j++) {
        s[0][j] = m[0][j] + m[1][j] + m[2][j] + m[3][j] + m[4][j];
        s[1][j] = m[1][j] - m[2][j] + 2.f * (m[3][j] - m[4][j]);
        s[2][j] = m[1][j] + m[2][j] + 4.f * (m[3][j] + m[4][j]);
        s[3][j] = m[1][j] - m[2][j] + 8.f * (m[3][j] - m[4][j]) + m[5][j];
    }
    const float bs = bias[co];
    int b = tile >> 8, t = tile & 255, ty = t >> 4, tx = t & 15;
    float* dst0 = out + (((size_t)b * Cout + co) << 12) + (4 * ty) * 64 + 4 * tx;
#pragma unroll
    for (int i = 0; i < 4; i++) {
        float y0 = s[i][0] + s[i][1] + s[i][2] + s[i][3] + s[i][4] + bs;
        float y1 = s[i][1] - s[i][2] + 2.f * (s[i][3] - s[i][4]) + bs;
        float y2 = s[i][1] + s[i][2] + 4.f * (s[i][3] + s[i][4]) + bs;
        float y3 = s[i][1] - s[i][2] + 8.f * (s[i][3] - s[i][4]) + s[i][5] + bs;
        if (RELU) {
            y0 = fmaxf(y0, 0.f); y1 = fmaxf(y1, 0.f);
            y2 = fmaxf(y2, 0.f); y3 = fmaxf(y3, 0.f);
        }
        float* dst = dst0 + i * 64;
        dst[0] = y0; dst[1] = y1; dst[2] = y2; dst[3] = y3;
    }
}

// --------------------- 1x1 conv + residual add (scalar) ----------------------
__global__ void __launch_bounds__(256)
conv1x1_acc_k(const float* __restrict__ in, const float* __restrict__ wp,
              const float* __restrict__ bias, float* __restrict__ out,
              int Cin, int Cout) {
    const int cout0 = blockIdx.x * 128;
    const int by = blockIdx.y;
    const int b = by >> 6, y = by & 63;
    const int tid = threadIdx.x;
    const int tx = tid & 15, ty = tid >> 4;

    __shared__ __align__(16) float Ws[16][128];
    __shared__ __align__(16) float Xs[16][64];

    float acc[8][4];
#pragma unroll
    for (int i = 0; i < 8; i++)
#pragma unroll
        for (int j = 0; j < 4; j++) acc[i][j] = 0.f;

    const int l = tid * 4;
    const int kW = l >> 7, coW = l & 127;
    const int kX = l >> 6, pxX = l & 63;
    const float* inrow = in + (size_t)b * Cin * 4096 + (size_t)y * 64;

    for (int c0 = 0; c0 < Cin; c0 += 16) {
        __syncthreads();
        *(float4*)&Ws[kW][coW] =
            *(const float4*)(wp + (size_t)(c0 + kW) * Cout + cout0 + coW);
        *(float4*)&Ws[kW + 8][coW] =
            *(const float4*)(wp + (size_t)(c0 + kW + 8) * Cout + cout0 + coW);
        *(float4*)&Xs[kX][pxX] =
            *(const float4*)(inrow + (size_t)(c0 + kX) * 4096 + pxX);
        __syncthreads();
#pragma unroll
        for (int k = 0; k < 16; k++) {
            const float4 bv = *(const float4*)&Xs[k][tx * 4];
            const float4 a0 = *(const float4*)&Ws[k][ty * 8];
            const float4 a1 = *(const float4*)&Ws[k][ty * 8 + 4];
            const float bj[4] = {bv.x, bv.y, bv.z, bv.w};
            const float ai[8] = {a0.x, a0.y, a0.z, a0.w, a1.x, a1.y, a1.z, a1.w};
#pragma unroll
            for (int i = 0; i < 8; i++)
#pragma unroll
                for (int j = 0; j < 4; j++)
                    acc[i][j] = fmaf(ai[i], bj[j], acc[i][j]);
        }
    }

#pragma unroll
    for (int i = 0; i < 8; i++) {
        const int co = cout0 + ty * 8 + i;
        const float bs = bias[co];
        float* orow = out + (((size_t)b * Cout + co) * 64 + y) * 64;
        float4 cur = *(float4*)(orow + tx * 4);
        cur.x += acc[i][0] + bs; cur.y += acc[i][1] + bs;
        cur.z += acc[i][2] + bs; cur.w += acc[i][3] + bs;
        *(float4*)(orow + tx * 4) = cur;
    }
}

// ------------------------------- VQ argmin -----------------------------------
__global__ void __launch_bounds__(256)
vq_argmin_k(const float* __restrict__ z, const float* __restrict__ cbT,
            const float* __restrict__ cn, const float* __restrict__ zn,
            unsigned long long* __restrict__ bestkey) {
    const int code0 = blockIdx.x * 64;
    const int by = blockIdx.y;
    const int b = by >> 6, y = by & 63;
    const int tid = threadIdx.x;
    const int tx = tid & 15, ty = tid >> 4;

    __shared__ __align__(16) float Cs[16][64];
    __shared__ __align__(16) float Zs[16][64];
    __shared__ unsigned long long red[16][64];

    float acc[4][4];
#pragma unroll
    for (int i = 0; i < 4; i++)
#pragma unroll
        for (int j = 0; j < 4; j++) acc[i][j] = 0.f;

    const int l = tid * 4;
    const int k = l >> 6, c = l & 63;

    for (int d0 = 0; d0 < 256; d0 += 16) {
        __syncthreads();
        *(float4*)&Cs[k][c] = *(const float4*)&cbT[(size_t)(d0 + k) * 1024 + code0 + c];
        *(float4*)&Zs[k][c] =
            *(const float4*)&z[(((size_t)b * 256 + d0 + k) * 64 + y) * 64 + c];
        __syncthreads();
#pragma unroll
        for (int kk = 0; kk < 16; kk++) {
            const float4 av = *(const float4*)&Cs[kk][ty * 4];
            const float4 bv = *(const float4*)&Zs[kk][tx * 4];
            const float ai[4] = {av.x, av.y, av.z, av.w};
            const float bj[4] = {bv.x, bv.y, bv.z, bv.w};
#pragma unroll
            for (int i = 0; i < 4; i++)
#pragma unroll
                for (int j = 0; j < 4; j++)
                    acc[i][j] = fmaf(ai[i], bj[j], acc[i][j]);
        }
    }

#pragma unroll
    for (int j = 0; j < 4; j++) {
        const float znv = zn[by * 64 + tx * 4 + j];
        unsigned long long best = 0xFFFFFFFFFFFFFFFFull;
#pragma unroll
        for (int i = 0; i < 4; i++) {
            const int code = code0 + ty * 4 + i;
            const float s = (znv - 2.f * acc[i][j]) + cn[code];
            unsigned int u = __float_as_uint(s);
            unsigned int k32 = (u >> 31) ? ~u : (u | 0x80000000u);
            unsigned long long key = ((unsigned long long)k32 << 32) | (unsigned int)code;
            best = (key < best) ? key : best;
        }
        red[ty][tx * 4 + j] = best;
    }
    __syncthreads();
    for (int st = 8; st; st >>= 1) {
        if (ty < st) {
#pragma unroll
            for (int j = 0; j < 4; j++) {
                unsigned long long a = red[ty][tx * 4 + j];
                unsigned long long b2 = red[ty + st][tx * 4 + j];
                red[ty][tx * 4 + j] = (b2 < a) ? b2 : a;
            }
        }
        __syncthreads();
    }
    if (ty == 0) {
#pragma unroll
        for (int j = 0; j < 4; j++)
            atomicMin(&bestkey[by * 64 + tx * 4 + j], red[0][tx * 4 + j]);
    }
}

__global__ void vq_gather_k(const float* __restrict__ z, const float* __restrict__ cb,
                            const unsigned long long* __restrict__ bestkey,
                            float* __restrict__ zq, float* __restrict__ vqsum) {
    const int n = blockIdx.x;
    const int d = threadIdx.x;
    const int idx = (int)(bestkey[n] & 0xFFFFFFFFull);
    const int b = n >> 12, rem = n & 4095;
    const float q = cb[idx * 256 + d];
    const size_t zoff = (((size_t)b * 256 + d) << 12) + rem;
    const float zv = z[zoff];
    const float diff = q - zv;
    zq[zoff] = zv + diff;
    float p = warpReduceSum(diff * diff);
    __shared__ float sh[8];
    if ((threadIdx.x & 31) == 0) sh[threadIdx.x >> 5] = p;
    __syncthreads();
    if (threadIdx.x == 0) {
        float t = 0.f;
#pragma unroll
        for (int i = 0; i < 8; i++) t += sh[i];
        atomicAdd(vqsum, t);
    }
}

// -------------------------------- deconv -------------------------------------
__global__ void deconv_k(const float* __restrict__ in, const float* __restrict__ w,
                         const float* __restrict__ bias, const float* __restrict__ x,
                         float* __restrict__ out, float* __restrict__ reconsum) {
    const int idx = blockIdx.x * blockDim.x + threadIdx.x;
    if (idx >= 393216) return;
    const int ox = idx & 127, oy = (idx >> 7) & 127;
    const int bo = idx >> 14;
    const int o = bo % 3, b = bo / 3;
    float acc = bias[o];
    const int kyp = (oy + 1) & 1, kxp = (ox + 1) & 1;
#pragma unroll
    for (int t = 0; t < 4; t++) {
        const int ky = kyp + 2 * (t >> 1);
        const int kx = kxp + 2 * (t & 1);
        const int ny = oy + 1 - ky, nx = ox + 1 - kx;
        if (ny < 0 || nx < 0) continue;
        const int iy = ny >> 1, ix = nx >> 1;
        if (iy >= 64 || ix >= 64) continue;
        const float* ip = in + (size_t)b * 256 * 4096 + iy * 64 + ix;
        const float* wpp = w + o * 16 + ky * 4 + kx;
        float a = 0.f;
        for (int c2 = 0; c2 < 256; c2++)
            a = fmaf(ip[(size_t)c2 * 4096], wpp[c2 * 48], a);
        acc += a;
    }
    out[idx] = acc;
    const float d = acc - x[idx];
    float p = warpReduceSum(d * d);
    if ((threadIdx.x & 31) == 0) atomicAdd(reconsum, p);
}

__global__ void finalize_k(float* __restrict__ out, const float* __restrict__ vqsum,
                           const float* __restrict__ reconsum) {
    const float recon = *reconsum * (1.f / 393216.f);
    const float vq = 1.25f * (*vqsum) * (1.f / 8388608.f);
    out[393216] = recon + vq;
    out[393217] = recon;
}

// --------------------------------- launch ------------------------------------
extern "C" void kernel_launch(void* const* d_in, const int* in_sizes, int n_in,
                              void* d_out, int out_size) {
    const float* x          = (const float*)d_in[0];
    const float* ec0_w      = (const float*)d_in[1];
    const float* ec0_b      = (const float*)d_in[2];
    const float* ebn0_g     = (const float*)d_in[3];
    const float* ebn0_b     = (const float*)d_in[4];
    const float* ec1_w      = (const float*)d_in[5];
    const float* ec1_b      = (const float*)d_in[6];
    const float* ebn1_g     = (const float*)d_in[7];
    const float* ebn1_b     = (const float*)d_in[8];
    const float* ec2_w      = (const float*)d_in[9];
    const float* ec2_b      = (const float*)d_in[10];
    const float* er_w1      = (const float*)d_in[11];
    const float* er_b1      = (const float*)d_in[12];
    const float* er_w2      = (const float*)d_in[13];
    const float* er_b2      = (const float*)d_in[14];
    const float* ec3_w      = (const float*)d_in[15];
    const float* ec3_b      = (const float*)d_in[16];
    const float* codebook   = (const float*)d_in[17];
    const float* dc0_w      = (const float*)d_in[18];
    const float* dc0_b      = (const float*)d_in[19];
    const float* dr_w1      = (const float*)d_in[20];
    const float* dr_b1      = (const float*)d_in[21];
    const float* dr_w2      = (const float*)d_in[22];
    const float* dr_b2      = (const float*)d_in[23];
    const float* dc1_w      = (const float*)d_in[24];
    const float* dc1_b      = (const float*)d_in[25];
    const float* dd_w       = (const float*)d_in[26];
    const float* dd_b       = (const float*)d_in[27];
    float* out = (float*)d_out;

    float *bufA, *bufB, *bufT, *bufZ, *V, *M;
    float *u4_1, *u4_2, *u4_3, *u4E1, *u4D0, *u4D1, *u4Dr1, *pwE2, *pwDr2;
    float *cbT, *cn, *zn, *bnsc, *bnsh, *vqsum, *reconsum;
    unsigned long long* bestkey;
    cudaGetSymbolAddress((void**)&bufA, g_bufA);
    cudaGetSymbolAddress((void**)&bufB, g_bufB);
    cudaGetSymbolAddress((void**)&bufT, g_bufT);
    cudaGetSymbolAddress((void**)&bufZ, g_bufZ);
    cudaGetSymbolAddress((void**)&V,    g_V);
    cudaGetSymbolAddress((void**)&M,    g_M);
    cudaGetSymbolAddress((void**)&u4_1, g_u4_1);
    cudaGetSymbolAddress((void**)&u4_2, g_u4_2);
    cudaGetSymbolAddress((void**)&u4_3, g_u4_3);
    cudaGetSymbolAddress((void**)&u4E1, g_u4E1);
    cudaGetSymbolAddress((void**)&u4D0, g_u4D0);
    cudaGetSymbolAddress((void**)&u4D1, g_u4D1);
    cudaGetSymbolAddress((void**)&u4Dr1, g_u4Dr1);
    cudaGetSymbolAddress((void**)&pwE2, g_pwE2);
    cudaGetSymbolAddress((void**)&pwDr2, g_pwDr2);
    cudaGetSymbolAddress((void**)&cbT,  g_cbT);
    cudaGetSymbolAddress((void**)&cn,   g_cnorm);
    cudaGetSymbolAddress((void**)&zn,   g_znorm);
    cudaGetSymbolAddress((void**)&bnsc, g_bnscale);
    cudaGetSymbolAddress((void**)&bnsh, g_bnshift);
    cudaGetSymbolAddress((void**)&vqsum, g_vqsum);
    cudaGetSymbolAddress((void**)&reconsum, g_reconsum);
    cudaGetSymbolAddress((void**)&bestkey, g_bestkey);

    const size_t resU4 = (size_t)36 * 512 * 128;   // per res layer (F4)

    // ---- weight transforms + packs + init ----
    wtrans4_k<<<512, 256>>>(ec1_w, u4_1, 1, 256, 512);
    wtrans4_k<<<1024, 256>>>(ec2_w, u4_2, 1, 512, 512);
    wtrans4_k<<<512, 256>>>(ec3_w, u4_3, 1, 512, 256);
    wtrans4_k<<<4096, 256>>>(er_w1, u4E1, 16, 512, 128);
    wtrans4_k<<<512, 256>>>(dc0_w, u4D0, 1, 256, 512);
    wtrans4_k<<<512, 256>>>(dc1_w, u4D1, 1, 512, 256);
    wtrans4_k<<<4096, 256>>>(dr_w1, u4Dr1, 16, 512, 128);
    pack1x1_k<<<2048, 256>>>(er_w2, pwE2, 16, 128, 512);
    pack1x1_k<<<2048, 256>>>(dr_w2, pwDr2, 16, 128, 512);
    packT_k<<<1024, 256>>>(codebook, cbT);
    init_k<<<128, 256>>>(bestkey, vqsum, reconsum);
    cnorm_k<<<1024, 256>>>(codebook, cn);

    // ---- encoder (all F4x4) ----
    conv0_k<<<32768, 256>>>(x, ec0_w, ec0_b, bufZ);
    bn_stats_k<<<256, 256>>>(bufZ, ebn0_g, ebn0_b, 256, bnsc, bnsh);
    bn_apply_k<<<32768, 256>>>(bufZ, bnsc, bnsh, 256, 8 * 256 * 4096);

    // conv1: 256 -> 512
    win4_in_k<false><<<2048, 256>>>(bufZ, V, 256);
    win_gemm_k<<<dim3(144, 32), 256>>>(u4_1, V, M, 256, 512, 2048);
    win4_out_k<false><<<4096, 256>>>(M, ec1_b, bufA, 512);
    bn_stats_k<<<512, 256>>>(bufA, ebn1_g, ebn1_b, 512, bnsc, bnsh);
    bn_apply_k<<<65536, 256>>>(bufA, bnsc, bnsh, 512, 8 * 512 * 4096);

    // conv2: 512 -> 512
    win4_in_k<false><<<4096, 256>>>(bufA, V, 512);
    win_gemm_k<<<dim3(144, 32), 256>>>(u4_2, V, M, 512, 512, 2048);
    win4_out_k<false><<<4096, 256>>>(M, ec2_b, bufB, 512);

    // encoder res stacks
    for (int blk = 0; blk < 16; blk++) {
        win4_in_k<true><<<4096, 256>>>(bufB, V, 512);
        win_gemm_k<<<dim3(36, 32), 256>>>(u4E1 + (size_t)blk * resU4, V, M, 512, 128, 2048);
        win4_out_k<true><<<1024, 256>>>(M, er_b1 + blk * 128, bufT, 128);
        conv1x1_acc_k<<<dim3(4, BH), 256>>>(
            bufT, pwE2 + (size_t)blk * 128 * 512, er_b2 + blk * 512, bufB, 128, 512);
        if ((blk & 3) == 3)
            relu_ip_k<<<65536, 256>>>(bufB, 8 * 512 * 4096);
    }

    // conv3: 512 -> 256
    win4_in_k<false><<<4096, 256>>>(bufB, V, 512);
    win_gemm_k<<<dim3(72, 32), 256>>>(u4_3, V, M, 512, 256, 2048);
    win4_out_k<false><<<2048, 256>>>(M, ec3_b, bufZ, 256);

    // ---- vector quantizer ----
    znorm_k<<<128, 256>>>(bufZ, zn);
    vq_argmin_k<<<dim3(16, BH), 256>>>(bufZ, cbT, cn, zn, bestkey);
    vq_gather_k<<<32768, 256>>>(bufZ, codebook, bestkey, bufA, vqsum);

    // ---- decoder (F4x4) ----
    win4_in_k<false><<<2048, 256>>>(bufA, V, 256);
    win_gemm_k<<<dim3(144, 32), 256>>>(u4D0, V, M, 256, 512, 2048);
    win4_out_k<false><<<4096, 256>>>(M, dc0_b, bufB, 512);

    for (int blk = 0; blk < 16; blk++) {
        win4_in_k<true><<<4096, 256>>>(bufB, V, 512);
        win_gemm_k<<<dim3(36, 32), 256>>>(u4Dr1 + (size_t)blk * resU4, V, M, 512, 128, 2048);
        win4_out_k<true><<<1024, 256>>>(M, dr_b1 + blk * 128, bufT, 128);
        conv1x1_acc_k<<<dim3(4, BH), 256>>>(
            bufT, pwDr2 + (size_t)blk * 128 * 512, dr_b2 + blk * 512, bufB, 128, 512);
        if ((blk & 3) == 3)
            relu_ip_k<<<65536, 256>>>(bufB, 8 * 512 * 4096);
    }

    win4_in_k<false><<<4096, 256>>>(bufB, V, 512);
    win_gemm_k<<<dim3(72, 32), 256>>>(u4D1, V, M, 512, 256, 2048);
    win4_out_k<true><<<2048, 256>>>(M, dc1_b, bufZ, 256);

    deconv_k<<<1536, 256>>>(bufZ, dd_w, dd_b, x, out, reconsum);
    finalize_k<<<1, 1>>>(out, vqsum, reconsum);
}

// round 14
// speedup vs baseline: 5.5611x; 1.0047x over previous
#include <cuda_runtime.h>
#include <math.h>

// ---------------------------------------------------------------------------
// VQ-VAE forward. x: [8,3,128,128]; encoder spatial 64x64. BH = 8*64 = 512.
// ALL 3x3 convs run as Winograd F(4x4,3x3): 16x16=256 tiles/image, 2048 total.
// ---------------------------------------------------------------------------

#define BH 512
#define NT4 2048   // 8 images * 16*16 tiles (F4)

// ------------------------------- scratch -----------------------------------
__device__ float g_bufA[16777216];   // [8,512,64,64]
__device__ float g_bufB[16777216];   // [8,512,64,64]
__device__ float g_bufT[4194304];    // [8,128,64,64]
__device__ float g_bufZ[8388608];    // [8,256,64,64]

__device__ float g_V[37748736];      // winograd input  [36][512][2048]
__device__ float g_M[37748736];      // winograd output [36][Cout][2048]

__device__ float g_u4_1 [4718592];   // conv1  U4 [36][256][512]
__device__ float g_u4_2 [9437184];   // conv2  U4 [36][512][512]
__device__ float g_u4_3 [4718592];   // conv3  U4 [36][512][256]
__device__ float g_u4E1 [37748736];  // enc res U4 [16 lay][36][512][128]
__device__ float g_u4D0 [4718592];   // dec c0 U4 [36][256][512]
__device__ float g_u4D1 [4718592];   // dec c1 U4 [36][512][256]
__device__ float g_u4Dr1[37748736];  // dec res U4 [16 lay][36][512][128]

__device__ float g_pwE2[1048576];    // enc res w2 packed [16][128][512]
__device__ float g_pwDr2[1048576];   // dec res w2 packed

__device__ float g_cbT [262144];     // codebook^T [256][1024]
__device__ float g_cnorm[1024];
__device__ float g_znorm[32768];
__device__ unsigned long long g_bestkey[32768];
__device__ float g_bnscale[512];
__device__ float g_bnshift[512];
__device__ float g_vqsum;
__device__ float g_reconsum;

// ---------------------------- small helpers --------------------------------
__device__ __forceinline__ float warpReduceSum(float v) {
#pragma unroll
    for (int s = 16; s > 0; s >>= 1) v += __shfl_down_sync(0xffffffffu, v, s);
    return v;
}

// ------------------------------ pack kernels -------------------------------
__global__ void pack1x1_k(const float* __restrict__ src, float* __restrict__ dst,
                          int nblk, int Cin, int Cout) {
    long long total = (long long)nblk * Cout * Cin;
    for (long long i = (long long)blockIdx.x * blockDim.x + threadIdx.x; i < total;
         i += (long long)gridDim.x * blockDim.x) {
        int ci = (int)(i % Cin);
        long long t = i / Cin;
        int co = (int)(t % Cout);
        int blk = (int)(t / Cout);
        dst[((long long)blk * Cin + ci) * Cout + co] = src[i];
    }
}

// F(4x4) weight transform: w [nblk][Cout][Cin][3][3] -> U [nblk][36][Cin][Cout]
__global__ void wtrans4_k(const float* __restrict__ w, float* __restrict__ U,
                          int nblk, int Cin, int Cout) {
    long long total = (long long)nblk * Cout * Cin;
    long long idx = (long long)blockIdx.x * blockDim.x + threadIdx.x;
    if (idx >= total) return;
    int ci = (int)(idx % Cin);
    long long rest = idx / Cin;
    int co = (int)(rest % Cout);
    int blk = (int)(rest / Cout);
    const float* g = w + idx * 9;
    float q[6][3];
#pragma unroll
    for (int j = 0; j < 3; j++) {
        float g0 = g[j], g1 = g[3 + j], g2 = g[6 + j];
        q[0][j] = 0.25f * g0;
        q[1][j] = (-g0 - g1 - g2) * (1.f / 6.f);
        q[2][j] = (-g0 + g1 - g2) * (1.f / 6.f);
        q[3][j] = g0 * (1.f / 24.f) + g1 * (1.f / 12.f) + g2 * (1.f / 6.f);
        q[4][j] = g0 * (1.f / 24.f) - g1 * (1.f / 12.f) + g2 * (1.f / 6.f);
        q[5][j] = g2;
    }
    size_t pl = (size_t)Cin * Cout;
    size_t base0 = (((size_t)blk * 36) * Cin + ci) * Cout + co;
#pragma unroll
    for (int i = 0; i < 6; i++) {
        float t0 = q[i][0], t1 = q[i][1], t2 = q[i][2];
        float u[6];
        u[0] = 0.25f * t0;
        u[1] = (-t0 - t1 - t2) * (1.f / 6.f);
        u[2] = (-t0 + t1 - t2) * (1.f / 6.f);
        u[3] = t0 * (1.f / 24.f) + t1 * (1.f / 12.f) + t2 * (1.f / 6.f);
        u[4] = t0 * (1.f / 24.f) - t1 * (1.f / 12.f) + t2 * (1.f / 6.f);
        u[5] = t2;
#pragma unroll
        for (int j = 0; j < 6; j++)
            U[base0 + (size_t)(i * 6 + j) * pl] = u[j];
    }
}

// codebook [1024][256] -> cbT [256][1024]
__global__ void packT_k(const float* __restrict__ src, float* __restrict__ dst) {
    int i = blockIdx.x * blockDim.x + threadIdx.x;
    if (i < 262144) {
        int d = i & 255, k = i >> 8;
        dst[d * 1024 + k] = src[i];
    }
}

__global__ void init_k(unsigned long long* bestkey, float* vqsum, float* reconsum) {
    int i = blockIdx.x * blockDim.x + threadIdx.x;
    if (i < 32768) bestkey[i] = 0xFFFFFFFFFFFFFFFFull;
    if (i == 0) { *vqsum = 0.f; *reconsum = 0.f; }
}

__global__ void cnorm_k(const float* __restrict__ cb, float* __restrict__ cn) {
    int k = blockIdx.x;
    float v = cb[k * 256 + threadIdx.x];
    float p = warpReduceSum(v * v);
    __shared__ float sh[8];
    if ((threadIdx.x & 31) == 0) sh[threadIdx.x >> 5] = p;
    __syncthreads();
    if (threadIdx.x == 0) {
        float t = 0.f;
#pragma unroll
        for (int i = 0; i < 8; i++) t += sh[i];
        cn[k] = t;
    }
}

__global__ void znorm_k(const float* __restrict__ z, float* __restrict__ zn) {
    int n = blockIdx.x * blockDim.x + threadIdx.x;
    if (n >= 32768) return;
    int b = n >> 12, rem = n & 4095;
    const float* zp = z + (((size_t)b * 256) << 12) + rem;
    float s = 0.f;
#pragma unroll 8
    for (int d = 0; d < 256; d++) {
        float v = zp[(size_t)d << 12];
        s = fmaf(v, v, s);
    }
    zn[n] = s;
}

// ------------------------------ conv0 (4x4 s2) ------------------------------
__global__ void conv0_k(const float* __restrict__ x, const float* __restrict__ w,
                        const float* __restrict__ bias, float* __restrict__ out) {
    int idx = blockIdx.x * blockDim.x + threadIdx.x;
    if (idx >= 8388608) return;
    int ox = idx & 63, oy = (idx >> 6) & 63, co = (idx >> 12) & 255, b = idx >> 20;
    float acc = bias[co];
    const float* wc = w + co * 48;
#pragma unroll
    for (int c = 0; c < 3; c++) {
        const float* xp = x + (size_t)(b * 3 + c) * 16384;
#pragma unroll
        for (int ky = 0; ky < 4; ky++) {
            int iy = oy * 2 - 1 + ky;
            if (iy < 0 || iy >= 128) continue;
#pragma unroll
            for (int kx = 0; kx < 4; kx++) {
                int ix = ox * 2 - 1 + kx;
                if (ix < 0 || ix >= 128) continue;
                acc = fmaf(xp[iy * 128 + ix], wc[c * 16 + ky * 4 + kx], acc);
            }
        }
    }
    out[idx] = acc;
}

// ------------------------------- batchnorm ----------------------------------
__global__ void bn_stats_k(const float* __restrict__ buf, const float* __restrict__ g,
                           const float* __restrict__ bb, int C,
                           float* __restrict__ scale, float* __restrict__ shift) {
    int c = blockIdx.x;
    int tid = threadIdx.x;
    double s = 0.0, s2 = 0.0;
    for (int t = tid; t < 8 * 4096; t += 256) {
        int b = t >> 12, off = t & 4095;
        float v = buf[(((size_t)b * C + c) << 12) + off];
        s += (double)v; s2 += (double)v * v;
    }
    __shared__ double sh[256], sh2[256];
    sh[tid] = s; sh2[tid] = s2;
    __syncthreads();
    for (int st = 128; st; st >>= 1) {
        if (tid < st) { sh[tid] += sh[tid + st]; sh2[tid] += sh2[tid + st]; }
        __syncthreads();
    }
    if (tid == 0) {
        double m = sh[0] / 32768.0;
        double v = sh2[0] / 32768.0 - m * m;
        double sc = (double)g[c] / sqrt(v + 1e-5);
        scale[c] = (float)sc;
        shift[c] = (float)((double)bb[c] - m * sc);
    }
}

__global__ void bn_apply_k(float* __restrict__ buf, const float* __restrict__ scale,
                           const float* __restrict__ shift, int C, int total) {
    int i = blockIdx.x * blockDim.x + threadIdx.x;
    if (i >= total) return;
    int c = (i >> 12) % C;
    buf[i] = fmaxf(fmaf(buf[i], scale[c], shift[c]), 0.f);
}

__global__ void relu_ip_k(float* __restrict__ buf, int total) {
    int i = blockIdx.x * blockDim.x + threadIdx.x;
    if (i < total) buf[i] = fmaxf(buf[i], 0.f);
}

// ---------------------- F(4x4): input transform -----------------------------
template <bool RELU>
__global__ void win4_in_k(const float* __restrict__ in, float* __restrict__ V, int Cin) {
    int idx = blockIdx.x * 256 + threadIdx.x;      // Cin * 2048
    if (idx >= (Cin << 11)) return;
    int tile = idx & 2047, ci = idx >> 11;
    int b = tile >> 8, t = tile & 255, ty = t >> 4, tx = t & 15;
    const float* src = in + (((size_t)b * Cin + ci) << 12);
    const int iy0 = 4 * ty - 1, ix0 = 4 * tx - 1;
    float d[6][6];
#pragma unroll
    for (int i = 0; i < 6; i++) {
        int iy = iy0 + i;
        bool yok = (iy >= 0 && iy < 64);
#pragma unroll
        for (int j = 0; j < 6; j++) {
            int ix = ix0 + j;
            float v = (yok && ix >= 0 && ix < 64) ? src[iy * 64 + ix] : 0.f;
            if (RELU) v = fmaxf(v, 0.f);
            d[i][j] = v;
        }
    }
    float w[6][6];
#pragma unroll
    for (int j = 0; j < 6; j++) {
        w[0][j] = 4.f * d[0][j] - 5.f * d[2][j] + d[4][j];
        w[1][j] = -4.f * d[1][j] - 4.f * d[2][j] + d[3][j] + d[4][j];
        w[2][j] = 4.f * d[1][j] - 4.f * d[2][j] - d[3][j] + d[4][j];
        w[3][j] = -2.f * d[1][j] - d[2][j] + 2.f * d[3][j] + d[4][j];
        w[4][j] = 2.f * d[1][j] - d[2][j] - 2.f * d[3][j] + d[4][j];
        w[5][j] = 4.f * d[1][j] - 5.f * d[3][j] + d[5][j];
    }
#pragma unroll
    for (int i = 0; i < 6; i++) {
        float v0 = 4.f * w[i][0] - 5.f * w[i][2] + w[i][4];
        float v1 = -4.f * w[i][1] - 4.f * w[i][2] + w[i][3] + w[i][4];
        float v2 = 4.f * w[i][1] - 4.f * w[i][2] - w[i][3] + w[i][4];
        float v3 = -2.f * w[i][1] - w[i][2] + 2.f * w[i][3] + w[i][4];
        float v4 = 2.f * w[i][1] - w[i][2] - 2.f * w[i][3] + w[i][4];
        float v5 = 4.f * w[i][1] - 5.f * w[i][3] + w[i][5];
        size_t pl = (size_t)512 * 2048;
        size_t base = ((size_t)(i * 6) * 512 + ci) * 2048 + tile;
        V[base]          = v0;
        V[base + pl]     = v1;
        V[base + 2 * pl] = v2;
        V[base + 3 * pl] = v3;
        V[base + 4 * pl] = v4;
        V[base + 5 * pl] = v5;
    }
}

// ---------------------- Winograd batched GEMM (scalar FFMA core) ------------
// M[r][co][tile] = sum_ci U[r][ci][co] * V[r][ci][tile]
__global__ void __launch_bounds__(256)
win_gemm_k(const float* __restrict__ U, const float* __restrict__ V,
           float* __restrict__ M, int Cin, int Cout, int ntiles) {
    const int coutTiles = Cout >> 7;
    const int r = blockIdx.x / coutTiles;
    const int co0 = (blockIdx.x % coutTiles) * 128;
    const int tile0 = blockIdx.y * 64;
    const int tid = threadIdx.x;
    const int tx = tid & 15, ty = tid >> 4;

    __shared__ __align__(16) float Ws[16][128];
    __shared__ __align__(16) float Xs[16][64];

    float acc[8][4];
#pragma unroll
    for (int i = 0; i < 8; i++)
#pragma unroll
        for (int j = 0; j < 4; j++) acc[i][j] = 0.f;

    const int l = tid * 4;
    const int kW = l >> 7, coW = l & 127;
    const int kX = l >> 6, pxX = l & 63;

    const float* Ur = U + (size_t)r * Cin * Cout;
    const float* Vr = V + (size_t)r * 512 * ntiles;

    for (int c0 = 0; c0 < Cin; c0 += 16) {
        __syncthreads();
        *(float4*)&Ws[kW][coW] =
            *(const float4*)(Ur + (size_t)(c0 + kW) * Cout + co0 + coW);
        *(float4*)&Ws[kW + 8][coW] =
            *(const float4*)(Ur + (size_t)(c0 + kW + 8) * Cout + co0 + coW);
        *(float4*)&Xs[kX][pxX] =
            *(const float4*)(Vr + (size_t)(c0 + kX) * ntiles + tile0 + pxX);
        __syncthreads();
#pragma unroll
        for (int k = 0; k < 16; k++) {
            const float4 bv = *(const float4*)&Xs[k][tx * 4];
            const float4 a0 = *(const float4*)&Ws[k][ty * 8];
            const float4 a1 = *(const float4*)&Ws[k][ty * 8 + 4];
            const float bj[4] = {bv.x, bv.y, bv.z, bv.w};
            const float ai[8] = {a0.x, a0.y, a0.z, a0.w, a1.x, a1.y, a1.z, a1.w};
#pragma unroll
            for (int i = 0; i < 8; i++)
#pragma unroll
                for (int j = 0; j < 4; j++)
                    acc[i][j] = fmaf(ai[i], bj[j], acc[i][j]);
        }
    }

#pragma unroll
    for (int i = 0; i < 8; i++) {
        const int co = co0 + ty * 8 + i;
        float* orow = M + ((size_t)r * Cout + co) * ntiles + tile0;
        *(float4*)(orow + tx * 4) = make_float4(acc[i][0], acc[i][1], acc[i][2], acc[i][3]);
    }
}

// ---------------------- F(4x4): inverse transform ---------------------------
template <bool RELU>
__global__ void win4_out_k(const float* __restrict__ M, const float* __restrict__ bias,
                           float* __restrict__ out, int Cout) {
    int idx = blockIdx.x * 256 + threadIdx.x;      // Cout * 2048
    if (idx >= (Cout << 11)) return;
    int tile = idx & 2047, co = idx >> 11;
    float m[6][6];
#pragma unroll
    for (int i = 0; i < 6; i++)
#pragma unroll
        for (int j = 0; j < 6; j++)
            m[i][j] = M[((size_t)(i * 6 + j) * Cout + co) * 2048 + tile];
    float s[4][6];
#pragma unroll
    for (int j = 0; j < 6; j++) {
        s[0][j] = m[0][j] + m[1][j] + m[2][j] + m[3][j] + m[4][j];
        s[1][j] = m[1][j] - m[2][j] + 2.f * (m[3][j] - m[4][j]);
        s[2][j] = m[1][j] + m[2][j] + 4.f * (m[3][j] + m[4][j]);
        s[3][j] = m[1][j] - m[2][j] + 8.f * (m[3][j] - m[4][j]) + m[5][j];
    }
    const float bs = bias[co];
    int b = tile >> 8, t = tile & 255, ty = t >> 4, tx = t & 15;
    float* dst0 = out + (((size_t)b * Cout + co) << 12) + (4 * ty) * 64 + 4 * tx;
#pragma unroll
    for (int i = 0; i < 4; i++) {
        float y0 = s[i][0] + s[i][1] + s[i][2] + s[i][3] + s[i][4] + bs;
        float y1 = s[i][1] - s[i][2] + 2.f * (s[i][3] - s[i][4]) + bs;
        float y2 = s[i][1] + s[i][2] + 4.f * (s[i][3] + s[i][4]) + bs;
        float y3 = s[i][1] - s[i][2] + 8.f * (s[i][3] - s[i][4]) + s[i][5] + bs;
        if (RELU) {
            y0 = fmaxf(y0, 0.f); y1 = fmaxf(y1, 0.f);
            y2 = fmaxf(y2, 0.f); y3 = fmaxf(y3, 0.f);
        }
        float* dst = dst0 + i * 64;
        dst[0] = y0; dst[1] = y1; dst[2] = y2; dst[3] = y3;
    }
}

// --------------------- 1x1 conv + residual add (scalar) ----------------------
__global__ void __launch_bounds__(256)
conv1x1_acc_k(const float* __restrict__ in, const float* __restrict__ wp,
              const float* __restrict__ bias, float* __restrict__ out,
              int Cin, int Cout) {
    const int cout0 = blockIdx.x * 128;
    const int by = blockIdx.y;
    const int b = by >> 6, y = by & 63;
    const int tid = threadIdx.x;
    const int tx = tid & 15, ty = tid >> 4;

    __shared__ __align__(16) float Ws[16][128];
    __shared__ __align__(16) float Xs[16][64];

    float acc[8][4];
#pragma unroll
    for (int i = 0; i < 8; i++)
#pragma unroll
        for (int j = 0; j < 4; j++) acc[i][j] = 0.f;

    const int l = tid * 4;
    const int kW = l >> 7, coW = l & 127;
    const int kX = l >> 6, pxX = l & 63;
    const float* inrow = in + (size_t)b * Cin * 4096 + (size_t)y * 64;

    for (int c0 = 0; c0 < Cin; c0 += 16) {
        __syncthreads();
        *(float4*)&Ws[kW][coW] =
            *(const float4*)(wp + (size_t)(c0 + kW) * Cout + cout0 + coW);
        *(float4*)&Ws[kW + 8][coW] =
            *(const float4*)(wp + (size_t)(c0 + kW + 8) * Cout + cout0 + coW);
        *(float4*)&Xs[kX][pxX] =
            *(const float4*)(inrow + (size_t)(c0 + kX) * 4096 + pxX);
        __syncthreads();
#pragma unroll
        for (int k = 0; k < 16; k++) {
            const float4 bv = *(const float4*)&Xs[k][tx * 4];
            const float4 a0 = *(const float4*)&Ws[k][ty * 8];
            const float4 a1 = *(const float4*)&Ws[k][ty * 8 + 4];
            const float bj[4] = {bv.x, bv.y, bv.z, bv.w};
            const float ai[8] = {a0.x, a0.y, a0.z, a0.w, a1.x, a1.y, a1.z, a1.w};
#pragma unroll
            for (int i = 0; i < 8; i++)
#pragma unroll
                for (int j = 0; j < 4; j++)
                    acc[i][j] = fmaf(ai[i], bj[j], acc[i][j]);
        }
    }

#pragma unroll
    for (int i = 0; i < 8; i++) {
        const int co = cout0 + ty * 8 + i;
        const float bs = bias[co];
        float* orow = out + (((size_t)b * Cout + co) * 64 + y) * 64;
        float4 cur = *(float4*)(orow + tx * 4);
        cur.x += acc[i][0] + bs; cur.y += acc[i][1] + bs;
        cur.z += acc[i][2] + bs; cur.w += acc[i][3] + bs;
        *(float4*)(orow + tx * 4) = cur;
    }
}

// ------------------------------- VQ argmin -----------------------------------
__global__ void __launch_bounds__(256)
vq_argmin_k(const float* __restrict__ z, const float* __restrict__ cbT,
            const float* __restrict__ cn, const float* __restrict__ zn,
            unsigned long long* __restrict__ bestkey) {
    const int code0 = blockIdx.x * 64;
    const int by = blockIdx.y;
    const int b = by >> 6, y = by & 63;
    const int tid = threadIdx.x;
    const int tx = tid & 15, ty = tid >> 4;

    __shared__ __align__(16) float Cs[16][64];
    __shared__ __align__(16) float Zs[16][64];
    __shared__ unsigned long long red[16][64];

    float acc[4][4];
#pragma unroll
    for (int i = 0; i < 4; i++)
#pragma unroll
        for (int j = 0; j < 4; j++) acc[i][j] = 0.f;

    const int l = tid * 4;
    const int k = l >> 6, c = l & 63;

    for (int d0 = 0; d0 < 256; d0 += 16) {
        __syncthreads();
        *(float4*)&Cs[k][c] = *(const float4*)&cbT[(size_t)(d0 + k) * 1024 + code0 + c];
        *(float4*)&Zs[k][c] =
            *(const float4*)&z[(((size_t)b * 256 + d0 + k) * 64 + y) * 64 + c];
        __syncthreads();
#pragma unroll
        for (int kk = 0; kk < 16; kk++) {
            const float4 av = *(const float4*)&Cs[kk][ty * 4];
            const float4 bv = *(const float4*)&Zs[kk][tx * 4];
            const float ai[4] = {av.x, av.y, av.z, av.w};
            const float bj[4] = {bv.x, bv.y, bv.z, bv.w};
#pragma unroll
            for (int i = 0; i < 4; i++)
#pragma unroll
                for (int j = 0; j < 4; j++)
                    acc[i][j] = fmaf(ai[i], bj[j], acc[i][j]);
        }
    }

#pragma unroll
    for (int j = 0; j < 4; j++) {
        const float znv = zn[by * 64 + tx * 4 + j];
        unsigned long long best = 0xFFFFFFFFFFFFFFFFull;
#pragma unroll
        for (int i = 0; i < 4; i++) {
            const int code = code0 + ty * 4 + i;
            const float s = (znv - 2.f * acc[i][j]) + cn[code];
            unsigned int u = __float_as_uint(s);
            unsigned int k32 = (u >> 31) ? ~u : (u | 0x80000000u);
            unsigned long long key = ((unsigned long long)k32 << 32) | (unsigned int)code;
            best = (key < best) ? key : best;
        }
        red[ty][tx * 4 + j] = best;
    }
    __syncthreads();
    for (int st = 8; st; st >>= 1) {
        if (ty < st) {
#pragma unroll
            for (int j = 0; j < 4; j++) {
                unsigned long long a = red[ty][tx * 4 + j];
                unsigned long long b2 = red[ty + st][tx * 4 + j];
                red[ty][tx * 4 + j] = (b2 < a) ? b2 : a;
            }
        }
        __syncthreads();
    }
    if (ty == 0) {
#pragma unroll
        for (int j = 0; j < 4; j++)
            atomicMin(&bestkey[by * 64 + tx * 4 + j], red[0][tx * 4 + j]);
    }
}

__global__ void vq_gather_k(const float* __restrict__ z, const float* __restrict__ cb,
                            const unsigned long long* __restrict__ bestkey,
                            float* __restrict__ zq, float* __restrict__ vqsum) {
    const int n = blockIdx.x;
    const int d = threadIdx.x;
    const int idx = (int)(bestkey[n] & 0xFFFFFFFFull);
    const int b = n >> 12, rem = n & 4095;
    const float q = cb[idx * 256 + d];
    const size_t zoff = (((size_t)b * 256 + d) << 12) + rem;
    const float zv = z[zoff];
    const float diff = q - zv;
    zq[zoff] = zv + diff;
    float p = warpReduceSum(diff * diff);
    __shared__ float sh[8];
    if ((threadIdx.x & 31) == 0) sh[threadIdx.x >> 5] = p;
    __syncthreads();
    if (threadIdx.x == 0) {
        float t = 0.f;
#pragma unroll
        for (int i = 0; i < 8; i++) t += sh[i];
        atomicAdd(vqsum, t);
    }
}

// -------------------------------- deconv -------------------------------------
__global__ void deconv_k(const float* __restrict__ in, const float* __restrict__ w,
                         const float* __restrict__ bias, const float* __restrict__ x,
                         float* __restrict__ out, float* __restrict__ reconsum) {
    const int idx = blockIdx.x * blockDim.x + threadIdx.x;
    if (idx >= 393216) return;
    const int ox = idx & 127, oy = (idx >> 7) & 127;
    const int bo = idx >> 14;
    const int o = bo % 3, b = bo / 3;
    float acc = bias[o];
    const int kyp = (oy + 1) & 1, kxp = (ox + 1) & 1;
#pragma unroll
    for (int t = 0; t < 4; t++) {
        const int ky = kyp + 2 * (t >> 1);
        const int kx = kxp + 2 * (t & 1);
        const int ny = oy + 1 - ky, nx = ox + 1 - kx;
        if (ny < 0 || nx < 0) continue;
        const int iy = ny >> 1, ix = nx >> 1;
        if (iy >= 64 || ix >= 64) continue;
        const float* ip = in + (size_t)b * 256 * 4096 + iy * 64 + ix;
        const float* wpp = w + o * 16 + ky * 4 + kx;
        float a = 0.f;
        for (int c2 = 0; c2 < 256; c2++)
            a = fmaf(ip[(size_t)c2 * 4096], wpp[c2 * 48], a);
        acc += a;
    }
    out[idx] = acc;
    const float d = acc - x[idx];
    float p = warpReduceSum(d * d);
    if ((threadIdx.x & 31) == 0) atomicAdd(reconsum, p);
}

__global__ void finalize_k(float* __restrict__ out, const float* __restrict__ vqsum,
                           const float* __restrict__ reconsum) {
    const float recon = *reconsum * (1.f / 393216.f);
    const float vq = 1.25f * (*vqsum) * (1.f / 8388608.f);
    out[393216] = recon + vq;
    out[393217] = recon;
}

// --------------------------------- launch ------------------------------------
extern "C" void kernel_launch(void* const* d_in, const int* in_sizes, int n_in,
                              void* d_out, int out_size) {
    const float* x          = (const float*)d_in[0];
    const float* ec0_w      = (const float*)d_in[1];
    const float* ec0_b      = (const float*)d_in[2];
    const float* ebn0_g     = (const float*)d_in[3];
    const float* ebn0_b     = (const float*)d_in[4];
    const float* ec1_w      = (const float*)d_in[5];
    const float* ec1_b      = (const float*)d_in[6];
    const float* ebn1_g     = (const float*)d_in[7];
    const float* ebn1_b     = (const float*)d_in[8];
    const float* ec2_w      = (const float*)d_in[9];
    const float* ec2_b      = (const float*)d_in[10];
    const float* er_w1      = (const float*)d_in[11];
    const float* er_b1      = (const float*)d_in[12];
    const float* er_w2      = (const float*)d_in[13];
    const float* er_b2      = (const float*)d_in[14];
    const float* ec3_w      = (const float*)d_in[15];
    const float* ec3_b      = (const float*)d_in[16];
    const float* codebook   = (const float*)d_in[17];
    const float* dc0_w      = (const float*)d_in[18];
    const float* dc0_b      = (const float*)d_in[19];
    const float* dr_w1      = (const float*)d_in[20];
    const float* dr_b1      = (const float*)d_in[21];
    const float* dr_w2      = (const float*)d_in[22];
    const float* dr_b2      = (const float*)d_in[23];
    const float* dc1_w      = (const float*)d_in[24];
    const float* dc1_b      = (const float*)d_in[25];
    const float* dd_w       = (const float*)d_in[26];
    const float* dd_b       = (const float*)d_in[27];
    float* out = (float*)d_out;

    float *bufA, *bufB, *bufT, *bufZ, *V, *M;
    float *u4_1, *u4_2, *u4_3, *u4E1, *u4D0, *u4D1, *u4Dr1, *pwE2, *pwDr2;
    float *cbT, *cn, *zn, *bnsc, *bnsh, *vqsum, *reconsum;
    unsigned long long* bestkey;
    cudaGetSymbolAddress((void**)&bufA, g_bufA);
    cudaGetSymbolAddress((void**)&bufB, g_bufB);
    cudaGetSymbolAddress((void**)&bufT, g_bufT);
    cudaGetSymbolAddress((void**)&bufZ, g_bufZ);
    cudaGetSymbolAddress((void**)&V,    g_V);
    cudaGetSymbolAddress((void**)&M,    g_M);
    cudaGetSymbolAddress((void**)&u4_1, g_u4_1);
    cudaGetSymbolAddress((void**)&u4_2, g_u4_2);
    cudaGetSymbolAddress((void**)&u4_3, g_u4_3);
    cudaGetSymbolAddress((void**)&u4E1, g_u4E1);
    cudaGetSymbolAddress((void**)&u4D0, g_u4D0);
    cudaGetSymbolAddress((void**)&u4D1, g_u4D1);
    cudaGetSymbolAddress((void**)&u4Dr1, g_u4Dr1);
    cudaGetSymbolAddress((void**)&pwE2, g_pwE2);
    cudaGetSymbolAddress((void**)&pwDr2, g_pwDr2);
    cudaGetSymbolAddress((void**)&cbT,  g_cbT);
    cudaGetSymbolAddress((void**)&cn,   g_cnorm);
    cudaGetSymbolAddress((void**)&zn,   g_znorm);
    cudaGetSymbolAddress((void**)&bnsc, g_bnscale);
    cudaGetSymbolAddress((void**)&bnsh, g_bnshift);
    cudaGetSymbolAddress((void**)&vqsum, g_vqsum);
    cudaGetSymbolAddress((void**)&reconsum, g_reconsum);
    cudaGetSymbolAddress((void**)&bestkey, g_bestkey);

    const size_t resU4 = (size_t)36 * 512 * 128;   // per res layer (F4)

    // ---- weight transforms + packs + init ----
    wtrans4_k<<<512, 256>>>(ec1_w, u4_1, 1, 256, 512);
    wtrans4_k<<<1024, 256>>>(ec2_w, u4_2, 1, 512, 512);
    wtrans4_k<<<512, 256>>>(ec3_w, u4_3, 1, 512, 256);
    wtrans4_k<<<4096, 256>>>(er_w1, u4E1, 16, 512, 128);
    wtrans4_k<<<512, 256>>>(dc0_w, u4D0, 1, 256, 512);
    wtrans4_k<<<512, 256>>>(dc1_w, u4D1, 1, 512, 256);
    wtrans4_k<<<4096, 256>>>(dr_w1, u4Dr1, 16, 512, 128);
    pack1x1_k<<<2048, 256>>>(er_w2, pwE2, 16, 128, 512);
    pack1x1_k<<<2048, 256>>>(dr_w2, pwDr2, 16, 128, 512);
    packT_k<<<1024, 256>>>(codebook, cbT);
    init_k<<<128, 256>>>(bestkey, vqsum, reconsum);
    cnorm_k<<<1024, 256>>>(codebook, cn);

    // ---- encoder (all F4x4) ----
    conv0_k<<<32768, 256>>>(x, ec0_w, ec0_b, bufZ);
    bn_stats_k<<<256, 256>>>(bufZ, ebn0_g, ebn0_b, 256, bnsc, bnsh);
    bn_apply_k<<<32768, 256>>>(bufZ, bnsc, bnsh, 256, 8 * 256 * 4096);

    // conv1: 256 -> 512
    win4_in_k<false><<<2048, 256>>>(bufZ, V, 256);
    win_gemm_k<<<dim3(144, 32), 256>>>(u4_1, V, M, 256, 512, 2048);
    win4_out_k<false><<<4096, 256>>>(M, ec1_b, bufA, 512);
    bn_stats_k<<<512, 256>>>(bufA, ebn1_g, ebn1_b, 512, bnsc, bnsh);
    bn_apply_k<<<65536, 256>>>(bufA, bnsc, bnsh, 512, 8 * 512 * 4096);

    // conv2: 512 -> 512
    win4_in_k<false><<<4096, 256>>>(bufA, V, 512);
    win_gemm_k<<<dim3(144, 32), 256>>>(u4_2, V, M, 512, 512, 2048);
    win4_out_k<false><<<4096, 256>>>(M, ec2_b, bufB, 512);

    // encoder res stacks
    for (int blk = 0; blk < 16; blk++) {
        win4_in_k<true><<<4096, 256>>>(bufB, V, 512);
        win_gemm_k<<<dim3(36, 32), 256>>>(u4E1 + (size_t)blk * resU4, V, M, 512, 128, 2048);
        win4_out_k<true><<<1024, 256>>>(M, er_b1 + blk * 128, bufT, 128);
        conv1x1_acc_k<<<dim3(4, BH), 256>>>(
            bufT, pwE2 + (size_t)blk * 128 * 512, er_b2 + blk * 512, bufB, 128, 512);
        if ((blk & 3) == 3)
            relu_ip_k<<<65536, 256>>>(bufB, 8 * 512 * 4096);
    }

    // conv3: 512 -> 256
    win4_in_k<false><<<4096, 256>>>(bufB, V, 512);
    win_gemm_k<<<dim3(72, 32), 256>>>(u4_3, V, M, 512, 256, 2048);
    win4_out_k<false><<<2048, 256>>>(M, ec3_b, bufZ, 256);

    // ---- vector quantizer ----
    znorm_k<<<128, 256>>>(bufZ, zn);
    vq_argmin_k<<<dim3(16, BH), 256>>>(bufZ, cbT, cn, zn, bestkey);
    vq_gather_k<<<32768, 256>>>(bufZ, codebook, bestkey, bufA, vqsum);

    // ---- decoder (F4x4) ----
    win4_in_k<false><<<2048, 256>>>(bufA, V, 256);
    win_gemm_k<<<dim3(144, 32), 256>>>(u4D0, V, M, 256, 512, 2048);
    win4_out_k<false><<<4096, 256>>>(M, dc0_b, bufB, 512);

    for (int blk = 0; blk < 16; blk++) {
        win4_in_k<true><<<4096, 256>>>(bufB, V, 512);
        win_gemm_k<<<dim3(36, 32), 256>>>(u4Dr1 + (size_t)blk * resU4, V, M, 512, 128, 2048);
        win4_out_k<true><<<1024, 256>>>(M, dr_b1 + blk * 128, bufT, 128);
        conv1x1_acc_k<<<dim3(4, BH), 256>>>(
            bufT, pwDr2 + (size_t)blk * 128 * 512, dr_b2 + blk * 512, bufB, 128, 512);
        if ((blk & 3) == 3)
            relu_ip_k<<<65536, 256>>>(bufB, 8 * 512 * 4096);
    }

    win4_in_k<false><<<4096, 256>>>(bufB, V, 512);
    win_gemm_k<<<dim3(72, 32), 256>>>(u4D1, V, M, 512, 256, 2048);
    win4_out_k<true><<<2048, 256>>>(M, dc1_b, bufZ, 256);

    deconv_k<<<1536, 256>>>(bufZ, dd_w, dd_b, x, out, reconsum);
    finalize_k<<<1, 1>>>(out, vqsum, reconsum);
}